// round 1
// baseline (speedup 1.0000x reference)
#include <cuda_runtime.h>
#include <mma.h>
#include <math.h>

using namespace nvcuda;

#define B_   2
#define S_   2048
#define D_   1024
#define H_   16
#define DK_  64
#define MTOT (B_ * S_)   // 4096

// Scratch (allocation-free rule: __device__ globals)
__device__ float g_Qp[MTOT * D_];
__device__ float g_Kp[MTOT * D_];
__device__ float g_Vp[MTOT * D_];
__device__ float g_At[MTOT * D_];

// ---------------------------------------------------------------------------
// GEMM: C[M,1024] = A[M,1024] @ W[1024,1024] + bias   (tf32 wmma, fp32 accum)
// Block tile 64x64, 8 warps (4x2), warp tile 16x32 (two 16x16 frags), BK=16.
// ---------------------------------------------------------------------------
__global__ __launch_bounds__(256) void gemm_bias_kernel(
    const float* __restrict__ A, const float* __restrict__ W,
    const float* __restrict__ bias, float* __restrict__ C)
{
    const int K = 1024, N = 1024;
    __shared__ __align__(32) float As[64][20];
    __shared__ __align__(32) float Bs[16][68];
    __shared__ __align__(32) float Cs[64][68];

    const int tid = threadIdx.x;
    const int wid = tid >> 5;
    const int wr  = wid >> 1;    // 0..3
    const int wc  = wid & 1;     // 0..1
    const int bm  = blockIdx.y * 64;
    const int bn  = blockIdx.x * 64;

    wmma::fragment<wmma::accumulator, 16, 16, 8, float> acc[2];
    wmma::fill_fragment(acc[0], 0.0f);
    wmma::fill_fragment(acc[1], 0.0f);

    for (int kt = 0; kt < K / 16; kt++) {
        // Load A tile 64x16 (64 rows x 4 float4)
        {
            int r  = tid >> 2;
            int c4 = tid & 3;
            float4 v = *(const float4*)(A + (size_t)(bm + r) * K + kt * 16 + c4 * 4);
            *(float4*)&As[r][c4 * 4] = v;
        }
        // Load W tile 16x64 (16 rows x 16 float4)
        {
            int r  = tid >> 4;
            int c4 = tid & 15;
            float4 v = *(const float4*)(W + (size_t)(kt * 16 + r) * N + bn + c4 * 4);
            *(float4*)&Bs[r][c4 * 4] = v;
        }
        __syncthreads();

        #pragma unroll
        for (int kk = 0; kk < 16; kk += 8) {
            wmma::fragment<wmma::matrix_a, 16, 16, 8, wmma::precision::tf32, wmma::row_major> a;
            wmma::load_matrix_sync(a, &As[wr * 16][kk], 20);
            #pragma unroll
            for (int i = 0; i < a.num_elements; i++) a.x[i] = wmma::__float_to_tf32(a.x[i]);
            #pragma unroll
            for (int f = 0; f < 2; f++) {
                wmma::fragment<wmma::matrix_b, 16, 16, 8, wmma::precision::tf32, wmma::row_major> b;
                wmma::load_matrix_sync(b, &Bs[kk][wc * 32 + f * 16], 68);
                #pragma unroll
                for (int i = 0; i < b.num_elements; i++) b.x[i] = wmma::__float_to_tf32(b.x[i]);
                wmma::mma_sync(acc[f], a, b, acc[f]);
            }
        }
        __syncthreads();
    }

    wmma::store_matrix_sync(&Cs[wr * 16][wc * 32],      acc[0], 68, wmma::mem_row_major);
    wmma::store_matrix_sync(&Cs[wr * 16][wc * 32 + 16], acc[1], 68, wmma::mem_row_major);
    __syncthreads();

    for (int i = tid; i < 1024; i += 256) {
        int r  = i >> 4;
        int c4 = i & 15;
        float4 v  = *(float4*)&Cs[r][c4 * 4];
        float4 bb = *(const float4*)(bias + bn + c4 * 4);
        v.x += bb.x; v.y += bb.y; v.z += bb.z; v.w += bb.w;
        *(float4*)(C + (size_t)(bm + r) * N + bn + c4 * 4) = v;
    }
}

// ---------------------------------------------------------------------------
// RoPE applied in place to g_Qp and g_Kp.
// One thread per (b, s, h, i) with i in [0,32): handles pair (i, i+32).
// ---------------------------------------------------------------------------
__global__ __launch_bounds__(256) void rope_kernel()
{
    int idx = blockIdx.x * blockDim.x + threadIdx.x;      // 2^21 total
    int i = idx & 31;
    int h = (idx >> 5) & (H_ - 1);
    int s = (idx >> 9) & (S_ - 1);
    int b = idx >> 20;

    double inv = exp(-((double)i / 32.0) * log(10000.0));
    double ang = (double)s * inv;
    float c  = (float)cos(ang);
    float sn = (float)sin(ang);

    size_t base = ((size_t)(b * S_ + s)) * D_ + h * DK_;
    float q1 = g_Qp[base + i];
    float q2 = g_Qp[base + i + 32];
    g_Qp[base + i]      = q1 * c - q2 * sn;
    g_Qp[base + i + 32] = q2 * c + q1 * sn;

    float k1 = g_Kp[base + i];
    float k2 = g_Kp[base + i + 32];
    g_Kp[base + i]      = k1 * c - k2 * sn;
    g_Kp[base + i + 32] = k2 * c + k1 * sn;
}

// ---------------------------------------------------------------------------
// Flash attention: grid (S/64, H, B), 256 threads. Online softmax, causal.
// Q tile pre-scaled by 1/sqrt(DK)=0.125. wmma tf32 for QK^T and PV.
// ---------------------------------------------------------------------------
#define LD 68
#define TILE_F (64 * LD)

__global__ __launch_bounds__(256) void flash_kernel()
{
    extern __shared__ __align__(128) float sm[];
    float (*Qs)[LD]   = (float(*)[LD])(sm);
    float (*Ks)[LD]   = (float(*)[LD])(sm + TILE_F);
    float (*Vs)[LD]   = (float(*)[LD])(sm + 2 * TILE_F);
    float (*Ssm)[LD]  = (float(*)[LD])(sm + 3 * TILE_F);
    float (*Oacc)[LD] = (float(*)[LD])(sm + 4 * TILE_F);
    float* mrow = sm + 5 * TILE_F;
    float* lrow = mrow + 64;
    float* rsc  = lrow + 64;

    const int qb = blockIdx.x, h = blockIdx.y, b = blockIdx.z;
    const int tid = threadIdx.x;
    const int wid = tid >> 5;
    const int wr  = wid >> 1;
    const int wc  = wid & 1;
    const int q0  = qb * 64;
    const int r   = tid >> 2;   // row 0..63 (softmax / epilogue mapping)
    const int p   = tid & 3;    // 4 threads per row, 16 cols each

    const float* Qg = g_Qp + ((size_t)b * S_ + q0) * D_ + h * DK_;

    // Load Q tile (scaled by 0.125) + init state
    for (int i = tid; i < 1024; i += 256) {
        int rr = i >> 4, c4 = i & 15;
        float4 v = *(const float4*)(Qg + (size_t)rr * D_ + c4 * 4);
        v.x *= 0.125f; v.y *= 0.125f; v.z *= 0.125f; v.w *= 0.125f;
        *(float4*)&Qs[rr][c4 * 4] = v;
        float4 z = make_float4(0.f, 0.f, 0.f, 0.f);
        *(float4*)&Oacc[rr][c4 * 4] = z;
    }
    if (tid < 64) { mrow[tid] = -1e30f; lrow[tid] = 0.0f; }
    __syncthreads();

    for (int kb = 0; kb <= qb; kb++) {
        const float* Kg = g_Kp + ((size_t)b * S_ + kb * 64) * D_ + h * DK_;
        const float* Vg = g_Vp + ((size_t)b * S_ + kb * 64) * D_ + h * DK_;
        for (int i = tid; i < 1024; i += 256) {
            int rr = i >> 4, c4 = i & 15;
            *(float4*)&Ks[rr][c4 * 4] = *(const float4*)(Kg + (size_t)rr * D_ + c4 * 4);
            *(float4*)&Vs[rr][c4 * 4] = *(const float4*)(Vg + (size_t)rr * D_ + c4 * 4);
        }
        __syncthreads();

        // S = Q @ K^T  (K^T via col_major fragment over row-major Ks)
        {
            wmma::fragment<wmma::accumulator, 16, 16, 8, float> sacc[2];
            wmma::fill_fragment(sacc[0], 0.0f);
            wmma::fill_fragment(sacc[1], 0.0f);
            #pragma unroll
            for (int kk = 0; kk < 64; kk += 8) {
                wmma::fragment<wmma::matrix_a, 16, 16, 8, wmma::precision::tf32, wmma::row_major> a;
                wmma::load_matrix_sync(a, &Qs[wr * 16][kk], LD);
                #pragma unroll
                for (int i = 0; i < a.num_elements; i++) a.x[i] = wmma::__float_to_tf32(a.x[i]);
                #pragma unroll
                for (int f = 0; f < 2; f++) {
                    wmma::fragment<wmma::matrix_b, 16, 16, 8, wmma::precision::tf32, wmma::col_major> bb;
                    wmma::load_matrix_sync(bb, &Ks[wc * 32 + f * 16][kk], LD);
                    #pragma unroll
                    for (int i = 0; i < bb.num_elements; i++) bb.x[i] = wmma::__float_to_tf32(bb.x[i]);
                    wmma::mma_sync(sacc[f], a, bb, sacc[f]);
                }
            }
            wmma::store_matrix_sync(&Ssm[wr * 16][wc * 32],      sacc[0], LD, wmma::mem_row_major);
            wmma::store_matrix_sync(&Ssm[wr * 16][wc * 32 + 16], sacc[1], LD, wmma::mem_row_major);
        }
        __syncthreads();

        // Online softmax (4 threads per row)
        {
            const bool diag = (kb == qb);
            float vals[16];
            float mx = -1e30f;
            #pragma unroll
            for (int j = 0; j < 16; j++) {
                int c = p * 16 + j;
                float sv = Ssm[r][c];
                if (diag && c > r) sv = -1e30f;
                vals[j] = sv;
                mx = fmaxf(mx, sv);
            }
            mx = fmaxf(mx, __shfl_xor_sync(0xffffffffu, mx, 1));
            mx = fmaxf(mx, __shfl_xor_sync(0xffffffffu, mx, 2));
            float mold = mrow[r];
            float mnew = fmaxf(mold, mx);
            float sum = 0.0f;
            #pragma unroll
            for (int j = 0; j < 16; j++) {
                float pj = __expf(vals[j] - mnew);
                Ssm[r][p * 16 + j] = pj;
                sum += pj;
            }
            sum += __shfl_xor_sync(0xffffffffu, sum, 1);
            sum += __shfl_xor_sync(0xffffffffu, sum, 2);
            if (p == 0) {
                float corr = __expf(mold - mnew);
                lrow[r] = lrow[r] * corr + sum;
                mrow[r] = mnew;
                rsc[r]  = corr;
            }
        }
        __syncthreads();

        // Rescale O accumulator
        {
            float corr = rsc[r];
            #pragma unroll
            for (int c4 = 0; c4 < 4; c4++) {
                float4 v = *(float4*)&Oacc[r][p * 16 + c4 * 4];
                v.x *= corr; v.y *= corr; v.z *= corr; v.w *= corr;
                *(float4*)&Oacc[r][p * 16 + c4 * 4] = v;
            }
        }
        __syncthreads();

        // O += P @ V
        {
            wmma::fragment<wmma::accumulator, 16, 16, 8, float> oacc[2];
            wmma::load_matrix_sync(oacc[0], &Oacc[wr * 16][wc * 32],      LD, wmma::mem_row_major);
            wmma::load_matrix_sync(oacc[1], &Oacc[wr * 16][wc * 32 + 16], LD, wmma::mem_row_major);
            #pragma unroll
            for (int kk = 0; kk < 64; kk += 8) {
                wmma::fragment<wmma::matrix_a, 16, 16, 8, wmma::precision::tf32, wmma::row_major> a;
                wmma::load_matrix_sync(a, &Ssm[wr * 16][kk], LD);
                #pragma unroll
                for (int i = 0; i < a.num_elements; i++) a.x[i] = wmma::__float_to_tf32(a.x[i]);
                #pragma unroll
                for (int f = 0; f < 2; f++) {
                    wmma::fragment<wmma::matrix_b, 16, 16, 8, wmma::precision::tf32, wmma::row_major> bb;
                    wmma::load_matrix_sync(bb, &Vs[kk][wc * 32 + f * 16], LD);
                    #pragma unroll
                    for (int i = 0; i < bb.num_elements; i++) bb.x[i] = wmma::__float_to_tf32(bb.x[i]);
                    wmma::mma_sync(oacc[f], a, bb, oacc[f]);
                }
            }
            wmma::store_matrix_sync(&Oacc[wr * 16][wc * 32],      oacc[0], LD, wmma::mem_row_major);
            wmma::store_matrix_sync(&Oacc[wr * 16][wc * 32 + 16], oacc[1], LD, wmma::mem_row_major);
        }
        __syncthreads();
    }

    // Epilogue: normalize by l and write to g_At (layout (B,S,D))
    {
        float inv_l = 1.0f / lrow[r];
        float* Og = g_At + ((size_t)b * S_ + q0) * D_ + h * DK_;
        #pragma unroll
        for (int c4 = 0; c4 < 4; c4++) {
            float4 v = *(float4*)&Oacc[r][p * 16 + c4 * 4];
            v.x *= inv_l; v.y *= inv_l; v.z *= inv_l; v.w *= inv_l;
            *(float4*)(Og + (size_t)r * D_ + p * 16 + c4 * 4) = v;
        }
    }
}

// ---------------------------------------------------------------------------
// Host launcher
// ---------------------------------------------------------------------------
extern "C" void kernel_launch(void* const* d_in, const int* in_sizes, int n_in,
                              void* d_out, int out_size)
{
    const float* q  = (const float*)d_in[0];
    const float* k  = (const float*)d_in[1];
    const float* v  = (const float*)d_in[2];
    // d_in[3] = mask (int32 causal tril) — handled analytically in flash_kernel
    const float* Wq = (const float*)d_in[4];
    const float* bq = (const float*)d_in[5];
    const float* Wk = (const float*)d_in[6];
    const float* bk = (const float*)d_in[7];
    const float* Wv = (const float*)d_in[8];
    const float* bv = (const float*)d_in[9];
    const float* Wo = (const float*)d_in[10];
    const float* bo = (const float*)d_in[11];
    float* out = (float*)d_out;

    float *Qp, *Kp, *Vp, *At;
    cudaGetSymbolAddress((void**)&Qp, g_Qp);
    cudaGetSymbolAddress((void**)&Kp, g_Kp);
    cudaGetSymbolAddress((void**)&Vp, g_Vp);
    cudaGetSymbolAddress((void**)&At, g_At);

    dim3 ggrid(1024 / 64, MTOT / 64);   // (16, 64)
    gemm_bias_kernel<<<ggrid, 256>>>(q, Wq, bq, Qp);
    gemm_bias_kernel<<<ggrid, 256>>>(k, Wk, bk, Kp);
    gemm_bias_kernel<<<ggrid, 256>>>(v, Wv, bv, Vp);

    rope_kernel<<<(B_ * S_ * H_ * 32) / 256, 256>>>();

    size_t smem = (5 * TILE_F + 3 * 64) * sizeof(float);   // ~87.8 KB
    cudaFuncSetAttribute(flash_kernel, cudaFuncAttributeMaxDynamicSharedMemorySize, (int)smem);
    flash_kernel<<<dim3(S_ / 64, H_, B_), 256, smem>>>();

    gemm_bias_kernel<<<ggrid, 256>>>(At, Wo, bo, out);
}

// round 2
// speedup vs baseline: 1.2401x; 1.2401x over previous
#include <cuda_runtime.h>
#include <mma.h>
#include <math.h>

using namespace nvcuda;

#define B_   2
#define S_   2048
#define D_   1024
#define H_   16
#define DK_  64
#define MTOT (B_ * S_)   // 4096

// Scratch (allocation-free rule: __device__ globals)
__device__ float g_Qp[MTOT * D_];
__device__ float g_Kp[MTOT * D_];
__device__ float g_Vp[MTOT * D_];
__device__ float g_At[MTOT * D_];
__device__ float g_cos[S_ * 32];
__device__ float g_sin[S_ * 32];

// ---------------------------------------------------------------------------
// RoPE table precompute: (s, i) for s in [0,2048), i in [0,32)
// ---------------------------------------------------------------------------
__global__ void table_kernel()
{
    int idx = blockIdx.x * blockDim.x + threadIdx.x;   // 65536
    int i = idx & 31;
    int s = idx >> 5;
    double inv = exp(-((double)i / 32.0) * log(10000.0));
    double ang = (double)s * inv;
    g_cos[idx] = (float)cos(ang);
    g_sin[idx] = (float)sin(ang);
}

// ---------------------------------------------------------------------------
// GEMM: C[M,1024] = A[M,1024] @ W[1024,1024] + bias, optional fused RoPE.
// Block tile 128x64, BK=16, double-buffered smem, 8 warps (4x2),
// warp tile 32x32 (2x2 frags of 16x16), tf32 wmma, fp32 accum.
// ---------------------------------------------------------------------------
#define GAS 2560   // one A buffer: 128*20 floats
#define GBS 1088   // one B buffer: 16*68 floats

__global__ __launch_bounds__(256, 1) void gemm_kernel(
    const float* __restrict__ A, const float* __restrict__ W,
    const float* __restrict__ bias, float* __restrict__ C, int rope)
{
    extern __shared__ __align__(128) float sm[];
    float* As = sm;                 // [2][128][20] = 5120 floats
    float* Bs = sm + 2 * GAS;       // [2][16][68]  = 2176 floats
    float (*Cs)[68] = (float(*)[68])sm;   // epilogue alias: 128*68 = 8704 floats

    const int K = 1024, N = 1024;
    const int tid = threadIdx.x;
    const int wid = tid >> 5;
    const int wr  = wid >> 1;    // 0..3 -> rows wr*32
    const int wc  = wid & 1;     // 0..1 -> cols wc*32
    const int bm  = blockIdx.y * 128;
    const int bn  = blockIdx.x * 64;

    const int ar  = tid >> 2;    // A-load row (0..63)
    const int ac4 = tid & 3;     // A-load float4 col
    const int br  = tid >> 4;    // B-load row (0..15)
    const int bc4 = tid & 15;    // B-load float4 col

    wmma::fragment<wmma::accumulator, 16, 16, 8, float> acc[2][2];
    #pragma unroll
    for (int s = 0; s < 2; s++)
        #pragma unroll
        for (int f = 0; f < 2; f++) wmma::fill_fragment(acc[s][f], 0.0f);

    // Prologue: tile kt=0 straight to smem buffer 0
    *(float4*)&As[ar * 20 + ac4 * 4] =
        *(const float4*)(A + (size_t)(bm + ar) * K + ac4 * 4);
    *(float4*)&As[(ar + 64) * 20 + ac4 * 4] =
        *(const float4*)(A + (size_t)(bm + ar + 64) * K + ac4 * 4);
    *(float4*)&Bs[br * 68 + bc4 * 4] =
        *(const float4*)(W + (size_t)br * N + bn + bc4 * 4);
    __syncthreads();

    for (int kt = 0; kt < 64; kt++) {
        const int cur = kt & 1, nxt = cur ^ 1;
        float4 ra0, ra1, rb;
        if (kt < 63) {
            ra0 = *(const float4*)(A + (size_t)(bm + ar) * K + (kt + 1) * 16 + ac4 * 4);
            ra1 = *(const float4*)(A + (size_t)(bm + ar + 64) * K + (kt + 1) * 16 + ac4 * 4);
            rb  = *(const float4*)(W + (size_t)((kt + 1) * 16 + br) * N + bn + bc4 * 4);
        }

        #pragma unroll
        for (int ks = 0; ks < 2; ks++) {
            wmma::fragment<wmma::matrix_a, 16, 16, 8, wmma::precision::tf32, wmma::row_major> a[2];
            wmma::fragment<wmma::matrix_b, 16, 16, 8, wmma::precision::tf32, wmma::row_major> bfr[2];
            #pragma unroll
            for (int s = 0; s < 2; s++) {
                wmma::load_matrix_sync(a[s], &As[cur * GAS + (wr * 32 + s * 16) * 20 + ks * 8], 20);
                #pragma unroll
                for (int i = 0; i < a[s].num_elements; i++) a[s].x[i] = wmma::__float_to_tf32(a[s].x[i]);
            }
            #pragma unroll
            for (int f = 0; f < 2; f++) {
                wmma::load_matrix_sync(bfr[f], &Bs[cur * GBS + (ks * 8) * 68 + wc * 32 + f * 16], 68);
                #pragma unroll
                for (int i = 0; i < bfr[f].num_elements; i++) bfr[f].x[i] = wmma::__float_to_tf32(bfr[f].x[i]);
            }
            #pragma unroll
            for (int s = 0; s < 2; s++)
                #pragma unroll
                for (int f = 0; f < 2; f++)
                    wmma::mma_sync(acc[s][f], a[s], bfr[f], acc[s][f]);
        }

        if (kt < 63) {
            *(float4*)&As[nxt * GAS + ar * 20 + ac4 * 4] = ra0;
            *(float4*)&As[nxt * GAS + (ar + 64) * 20 + ac4 * 4] = ra1;
            *(float4*)&Bs[nxt * GBS + br * 68 + bc4 * 4] = rb;
        }
        __syncthreads();
    }

    // Epilogue (Cs aliases As/Bs; all mma reads are done after final sync)
    #pragma unroll
    for (int s = 0; s < 2; s++)
        #pragma unroll
        for (int f = 0; f < 2; f++)
            wmma::store_matrix_sync(&Cs[wr * 32 + s * 16][wc * 32 + f * 16], acc[s][f], 68,
                                    wmma::mem_row_major);
    __syncthreads();

    if (rope) {
        // cols [0,32) pair with [32,64); one head per BN=64 tile
        for (int i = tid; i < 128 * 8; i += 256) {
            int r  = i >> 3;
            int c4 = i & 7;
            int c  = c4 * 4;
            int sg = (bm + r) & (S_ - 1);
            float4 v1 = *(float4*)&Cs[r][c];
            float4 v2 = *(float4*)&Cs[r][c + 32];
            float4 cw = *(const float4*)(g_cos + sg * 32 + c);
            float4 sw = *(const float4*)(g_sin + sg * 32 + c);
            float4 b1 = *(const float4*)(bias + bn + c);
            float4 b2 = *(const float4*)(bias + bn + c + 32);
            float4 o1, o2;
            o1.x = v1.x * cw.x - v2.x * sw.x + b1.x;  o2.x = v2.x * cw.x + v1.x * sw.x + b2.x;
            o1.y = v1.y * cw.y - v2.y * sw.y + b1.y;  o2.y = v2.y * cw.y + v1.y * sw.y + b2.y;
            o1.z = v1.z * cw.z - v2.z * sw.z + b1.z;  o2.z = v2.z * cw.z + v1.z * sw.z + b2.z;
            o1.w = v1.w * cw.w - v2.w * sw.w + b1.w;  o2.w = v2.w * cw.w + v1.w * sw.w + b2.w;
            *(float4*)(C + (size_t)(bm + r) * N + bn + c)      = o1;
            *(float4*)(C + (size_t)(bm + r) * N + bn + c + 32) = o2;
        }
    } else {
        for (int i = tid; i < 128 * 16; i += 256) {
            int r  = i >> 4;
            int c  = (i & 15) * 4;
            float4 v  = *(float4*)&Cs[r][c];
            float4 bb = *(const float4*)(bias + bn + c);
            v.x += bb.x; v.y += bb.y; v.z += bb.z; v.w += bb.w;
            *(float4*)(C + (size_t)(bm + r) * N + bn + c) = v;
        }
    }
}

// ---------------------------------------------------------------------------
// Flash attention v2: 128-row Q tile, 64-row K/V tiles, 256 threads (8 warps,
// 4x2). Q pre-scaled by 0.125 and pre-converted to tf32 fragments once.
// Online softmax with fused O-rescale. Causal via block loop kb < 2qb+2.
// ---------------------------------------------------------------------------
#define FLD 68

__global__ __launch_bounds__(256, 1) void flash_kernel()
{
    extern __shared__ __align__(128) float sm[];
    float (*Qs)[FLD]   = (float(*)[FLD])(sm);                 // 128 rows
    float (*Ks)[FLD]   = (float(*)[FLD])(sm + 128 * FLD);     // 64 rows
    float (*Vs)[FLD]   = (float(*)[FLD])(sm + 192 * FLD);     // 64 rows
    float (*Ssm)[FLD]  = (float(*)[FLD])(sm + 256 * FLD);     // 128 rows
    float (*Oacc)[FLD] = (float(*)[FLD])(sm + 384 * FLD);     // 128 rows
    float* mrow = sm + 512 * FLD;
    float* lrow = mrow + 128;

    const int qb = blockIdx.x, h = blockIdx.y, b = blockIdx.z;
    const int tid = threadIdx.x;
    const int wid = tid >> 5;
    const int wr  = wid >> 1;
    const int wc  = wid & 1;
    const int q0  = qb * 128;

    const float* Qg = g_Qp + ((size_t)b * S_ + q0) * D_ + h * DK_;

    for (int i = tid; i < 2048; i += 256) {
        int r = i >> 4, c = (i & 15) * 4;
        float4 v = *(const float4*)(Qg + (size_t)r * D_ + c);
        v.x *= 0.125f; v.y *= 0.125f; v.z *= 0.125f; v.w *= 0.125f;
        *(float4*)&Qs[r][c] = v;
        *(float4*)&Oacc[r][c] = make_float4(0.f, 0.f, 0.f, 0.f);
    }
    if (tid < 128) { mrow[tid] = -1e30f; lrow[tid] = 0.0f; }
    __syncthreads();

    // Pre-convert Q fragments (invariant across kb)
    wmma::fragment<wmma::matrix_a, 16, 16, 8, wmma::precision::tf32, wmma::row_major> aq[2][8];
    #pragma unroll
    for (int s = 0; s < 2; s++)
        #pragma unroll
        for (int kk = 0; kk < 8; kk++) {
            wmma::load_matrix_sync(aq[s][kk], &Qs[wr * 32 + s * 16][kk * 8], FLD);
            #pragma unroll
            for (int i = 0; i < aq[s][kk].num_elements; i++)
                aq[s][kk].x[i] = wmma::__float_to_tf32(aq[s][kk].x[i]);
        }

    const int nkb = 2 * qb + 2;
    for (int kb = 0; kb < nkb; kb++) {
        const float* Kg = g_Kp + ((size_t)b * S_ + kb * 64) * D_ + h * DK_;
        const float* Vg = g_Vp + ((size_t)b * S_ + kb * 64) * D_ + h * DK_;
        for (int i = tid; i < 1024; i += 256) {
            int r = i >> 4, c = (i & 15) * 4;
            *(float4*)&Ks[r][c] = *(const float4*)(Kg + (size_t)r * D_ + c);
            *(float4*)&Vs[r][c] = *(const float4*)(Vg + (size_t)r * D_ + c);
        }
        __syncthreads();

        // S = Q @ K^T
        {
            wmma::fragment<wmma::accumulator, 16, 16, 8, float> sacc[2][2];
            #pragma unroll
            for (int s = 0; s < 2; s++)
                #pragma unroll
                for (int f = 0; f < 2; f++) wmma::fill_fragment(sacc[s][f], 0.0f);
            #pragma unroll
            for (int kk = 0; kk < 8; kk++) {
                wmma::fragment<wmma::matrix_b, 16, 16, 8, wmma::precision::tf32, wmma::col_major> bb[2];
                #pragma unroll
                for (int f = 0; f < 2; f++) {
                    wmma::load_matrix_sync(bb[f], &Ks[wc * 32 + f * 16][kk * 8], FLD);
                    #pragma unroll
                    for (int i = 0; i < bb[f].num_elements; i++)
                        bb[f].x[i] = wmma::__float_to_tf32(bb[f].x[i]);
                }
                #pragma unroll
                for (int s = 0; s < 2; s++)
                    #pragma unroll
                    for (int f = 0; f < 2; f++)
                        wmma::mma_sync(sacc[s][f], aq[s][kk], bb[f], sacc[s][f]);
            }
            #pragma unroll
            for (int s = 0; s < 2; s++)
                #pragma unroll
                for (int f = 0; f < 2; f++)
                    wmma::store_matrix_sync(&Ssm[wr * 32 + s * 16][wc * 32 + f * 16], sacc[s][f],
                                            FLD, wmma::mem_row_major);
        }
        __syncthreads();

        // Online softmax + O rescale (4 threads per row, 2 row-halves)
        {
            const bool dz = (kb >= 2 * qb);
            const int p = tid & 3;
            #pragma unroll
            for (int half = 0; half < 2; half++) {
                int r = half * 64 + (tid >> 2);
                float vals[16];
                float mx = -1e30f;
                #pragma unroll
                for (int j = 0; j < 16; j++) {
                    int c = p * 16 + j;
                    float sv = Ssm[r][c];
                    if (dz && kb * 64 + c > q0 + r) sv = -1e30f;
                    vals[j] = sv;
                    mx = fmaxf(mx, sv);
                }
                mx = fmaxf(mx, __shfl_xor_sync(0xffffffffu, mx, 1));
                mx = fmaxf(mx, __shfl_xor_sync(0xffffffffu, mx, 2));
                float mold = mrow[r];
                float mnew = fmaxf(mold, mx);
                float sum = 0.0f;
                #pragma unroll
                for (int j = 0; j < 16; j++) {
                    float pj = __expf(vals[j] - mnew);
                    Ssm[r][p * 16 + j] = pj;
                    sum += pj;
                }
                sum += __shfl_xor_sync(0xffffffffu, sum, 1);
                sum += __shfl_xor_sync(0xffffffffu, sum, 2);
                float corr = __expf(mold - mnew);
                #pragma unroll
                for (int c4 = 0; c4 < 4; c4++) {
                    float4 v = *(float4*)&Oacc[r][p * 16 + c4 * 4];
                    v.x *= corr; v.y *= corr; v.z *= corr; v.w *= corr;
                    *(float4*)&Oacc[r][p * 16 + c4 * 4] = v;
                }
                if (p == 0) {
                    lrow[r] = lrow[r] * corr + sum;
                    mrow[r] = mnew;
                }
            }
        }
        __syncthreads();

        // O += P @ V
        {
            wmma::fragment<wmma::accumulator, 16, 16, 8, float> oacc[2][2];
            #pragma unroll
            for (int s = 0; s < 2; s++)
                #pragma unroll
                for (int f = 0; f < 2; f++)
                    wmma::load_matrix_sync(oacc[s][f], &Oacc[wr * 32 + s * 16][wc * 32 + f * 16],
                                           FLD, wmma::mem_row_major);
            #pragma unroll
            for (int kk = 0; kk < 8; kk++) {
                wmma::fragment<wmma::matrix_a, 16, 16, 8, wmma::precision::tf32, wmma::row_major> pa[2];
                wmma::fragment<wmma::matrix_b, 16, 16, 8, wmma::precision::tf32, wmma::row_major> vb[2];
                #pragma unroll
                for (int s = 0; s < 2; s++) {
                    wmma::load_matrix_sync(pa[s], &Ssm[wr * 32 + s * 16][kk * 8], FLD);
                    #pragma unroll
                    for (int i = 0; i < pa[s].num_elements; i++)
                        pa[s].x[i] = wmma::__float_to_tf32(pa[s].x[i]);
                }
                #pragma unroll
                for (int f = 0; f < 2; f++) {
                    wmma::load_matrix_sync(vb[f], &Vs[kk * 8][wc * 32 + f * 16], FLD);
                    #pragma unroll
                    for (int i = 0; i < vb[f].num_elements; i++)
                        vb[f].x[i] = wmma::__float_to_tf32(vb[f].x[i]);
                }
                #pragma unroll
                for (int s = 0; s < 2; s++)
                    #pragma unroll
                    for (int f = 0; f < 2; f++)
                        wmma::mma_sync(oacc[s][f], pa[s], vb[f], oacc[s][f]);
            }
            #pragma unroll
            for (int s = 0; s < 2; s++)
                #pragma unroll
                for (int f = 0; f < 2; f++)
                    wmma::store_matrix_sync(&Oacc[wr * 32 + s * 16][wc * 32 + f * 16], oacc[s][f],
                                            FLD, wmma::mem_row_major);
        }
        __syncthreads();
    }

    // Epilogue: normalize and write to g_At
    {
        const int p = tid & 3;
        float* Og = g_At + ((size_t)b * S_ + q0) * D_ + h * DK_;
        #pragma unroll
        for (int half = 0; half < 2; half++) {
            int r = half * 64 + (tid >> 2);
            float inv_l = 1.0f / lrow[r];
            #pragma unroll
            for (int c4 = 0; c4 < 4; c4++) {
                float4 v = *(float4*)&Oacc[r][p * 16 + c4 * 4];
                v.x *= inv_l; v.y *= inv_l; v.z *= inv_l; v.w *= inv_l;
                *(float4*)(Og + (size_t)r * D_ + p * 16 + c4 * 4) = v;
            }
        }
    }
}

// ---------------------------------------------------------------------------
// Host launcher
// ---------------------------------------------------------------------------
extern "C" void kernel_launch(void* const* d_in, const int* in_sizes, int n_in,
                              void* d_out, int out_size)
{
    const float* q  = (const float*)d_in[0];
    const float* k  = (const float*)d_in[1];
    const float* v  = (const float*)d_in[2];
    // d_in[3] = mask (causal tril) — handled analytically
    const float* Wq = (const float*)d_in[4];
    const float* bq = (const float*)d_in[5];
    const float* Wk = (const float*)d_in[6];
    const float* bk = (const float*)d_in[7];
    const float* Wv = (const float*)d_in[8];
    const float* bv = (const float*)d_in[9];
    const float* Wo = (const float*)d_in[10];
    const float* bo = (const float*)d_in[11];
    float* out = (float*)d_out;

    float *Qp, *Kp, *Vp, *At;
    cudaGetSymbolAddress((void**)&Qp, g_Qp);
    cudaGetSymbolAddress((void**)&Kp, g_Kp);
    cudaGetSymbolAddress((void**)&Vp, g_Vp);
    cudaGetSymbolAddress((void**)&At, g_At);

    table_kernel<<<S_ * 32 / 256, 256>>>();

    size_t gsmem = 128 * 68 * sizeof(float);   // 34.8 KB (epilogue alias dominates)
    cudaFuncSetAttribute(gemm_kernel, cudaFuncAttributeMaxDynamicSharedMemorySize, (int)gsmem);
    dim3 ggrid(1024 / 64, MTOT / 128);   // (16, 32)
    gemm_kernel<<<ggrid, 256, gsmem>>>(q, Wq, bq, Qp, 1);
    gemm_kernel<<<ggrid, 256, gsmem>>>(k, Wk, bk, Kp, 1);
    gemm_kernel<<<ggrid, 256, gsmem>>>(v, Wv, bv, Vp, 0);

    size_t fsmem = (512 * FLD + 256) * sizeof(float);   // ~140.3 KB
    cudaFuncSetAttribute(flash_kernel, cudaFuncAttributeMaxDynamicSharedMemorySize, (int)fsmem);
    flash_kernel<<<dim3(S_ / 128, H_, B_), 256, fsmem>>>();

    gemm_kernel<<<ggrid, 256, gsmem>>>(At, Wo, bo, out, 0);
}

// round 3
// speedup vs baseline: 1.4393x; 1.1607x over previous
#include <cuda_runtime.h>
#include <mma.h>
#include <math.h>

using namespace nvcuda;

#define B_   2
#define S_   2048
#define D_   1024
#define H_   16
#define DK_  64
#define MTOT (B_ * S_)   // 4096

__device__ float g_Qp[MTOT * D_];
__device__ float g_Kp[MTOT * D_];
__device__ float g_Vp[MTOT * D_];
__device__ float g_At[MTOT * D_];
__device__ float g_cos[S_ * 32];
__device__ float g_sin[S_ * 32];

__device__ __forceinline__ float tf32r(float x) {
    float r;
    asm("cvt.rna.tf32.f32 %0, %1;" : "=f"(r) : "f"(x));
    return r;
}
__device__ __forceinline__ float4 tf32r4(float4 v) {
    v.x = tf32r(v.x); v.y = tf32r(v.y); v.z = tf32r(v.z); v.w = tf32r(v.w);
    return v;
}

// ---------------------------------------------------------------------------
// RoPE tables
// ---------------------------------------------------------------------------
__global__ void table_kernel()
{
    int idx = blockIdx.x * blockDim.x + threadIdx.x;   // 65536
    int i = idx & 31;
    int s = idx >> 5;
    double inv = exp(-((double)i / 32.0) * log(10000.0));
    double ang = (double)s * inv;
    g_cos[idx] = (float)cos(ang);
    g_sin[idx] = (float)sin(ang);
}

// ---------------------------------------------------------------------------
// GEMM body: C[128-tile,128-tile] = A @ W + bias (+RoPE). tf32 pre-truncated
// at staging. BK=16 double-buffered, 8 warps (2x4), warp tile 64x32.
// ---------------------------------------------------------------------------
#define GA1 2560          // A buffer: 128*20
#define GB1 2112          // B buffer: 16*132

__device__ __forceinline__ void gemm_body(
    const float* __restrict__ A, const float* __restrict__ W,
    const float* __restrict__ bias, float* __restrict__ C, int rope, float* sm)
{
    float* As = sm;                 // [2][128][20]
    float* Bs = sm + 2 * GA1;       // [2][16][132]
    float (*Cs)[132] = (float(*)[132])sm;   // epilogue alias

    const int K = 1024, N = 1024;
    const int tid = threadIdx.x;
    const int wid = tid >> 5;
    const int wr  = wid >> 2;    // 0..1 -> rows wr*64
    const int wc  = wid & 3;     // 0..3 -> cols wc*32
    const int bm  = blockIdx.y * 128;
    const int bn  = blockIdx.x * 128;

    const int ar  = tid >> 2;    // 0..63 (rows ar, ar+64)
    const int ac4 = tid & 3;
    const int br  = tid >> 4;    // 0..15
    const int bc4 = tid & 15;    // cols bc4, bc4+16

    wmma::fragment<wmma::accumulator, 16, 16, 8, float> acc[4][2];
    #pragma unroll
    for (int s = 0; s < 4; s++)
        #pragma unroll
        for (int f = 0; f < 2; f++) wmma::fill_fragment(acc[s][f], 0.0f);

    // Prologue: kt=0 -> buffer 0 (truncate to tf32 at staging)
    *(float4*)&As[ar * 20 + ac4 * 4] =
        tf32r4(*(const float4*)(A + (size_t)(bm + ar) * K + ac4 * 4));
    *(float4*)&As[(ar + 64) * 20 + ac4 * 4] =
        tf32r4(*(const float4*)(A + (size_t)(bm + ar + 64) * K + ac4 * 4));
    *(float4*)&Bs[br * 132 + bc4 * 4] =
        tf32r4(*(const float4*)(W + (size_t)br * N + bn + bc4 * 4));
    *(float4*)&Bs[br * 132 + (bc4 + 16) * 4] =
        tf32r4(*(const float4*)(W + (size_t)br * N + bn + (bc4 + 16) * 4));
    __syncthreads();

    for (int kt = 0; kt < 64; kt++) {
        const int cur = kt & 1, nxt = cur ^ 1;
        float4 ra0, ra1, rb0, rb1;
        if (kt < 63) {
            ra0 = *(const float4*)(A + (size_t)(bm + ar) * K + (kt + 1) * 16 + ac4 * 4);
            ra1 = *(const float4*)(A + (size_t)(bm + ar + 64) * K + (kt + 1) * 16 + ac4 * 4);
            rb0 = *(const float4*)(W + (size_t)((kt + 1) * 16 + br) * N + bn + bc4 * 4);
            rb1 = *(const float4*)(W + (size_t)((kt + 1) * 16 + br) * N + bn + (bc4 + 16) * 4);
        }

        #pragma unroll
        for (int ks = 0; ks < 2; ks++) {
            wmma::fragment<wmma::matrix_a, 16, 16, 8, wmma::precision::tf32, wmma::row_major> a[4];
            wmma::fragment<wmma::matrix_b, 16, 16, 8, wmma::precision::tf32, wmma::row_major> bf[2];
            #pragma unroll
            for (int s = 0; s < 4; s++)
                wmma::load_matrix_sync(a[s], &As[cur * GA1 + (wr * 64 + s * 16) * 20 + ks * 8], 20);
            #pragma unroll
            for (int f = 0; f < 2; f++)
                wmma::load_matrix_sync(bf[f], &Bs[cur * GB1 + (ks * 8) * 132 + wc * 32 + f * 16], 132);
            #pragma unroll
            for (int s = 0; s < 4; s++)
                #pragma unroll
                for (int f = 0; f < 2; f++)
                    wmma::mma_sync(acc[s][f], a[s], bf[f], acc[s][f]);
        }

        if (kt < 63) {
            *(float4*)&As[nxt * GA1 + ar * 20 + ac4 * 4] = tf32r4(ra0);
            *(float4*)&As[nxt * GA1 + (ar + 64) * 20 + ac4 * 4] = tf32r4(ra1);
            *(float4*)&Bs[nxt * GB1 + br * 132 + bc4 * 4] = tf32r4(rb0);
            *(float4*)&Bs[nxt * GB1 + br * 132 + (bc4 + 16) * 4] = tf32r4(rb1);
        }
        __syncthreads();
    }

    #pragma unroll
    for (int s = 0; s < 4; s++)
        #pragma unroll
        for (int f = 0; f < 2; f++)
            wmma::store_matrix_sync(&Cs[wr * 64 + s * 16][wc * 32 + f * 16], acc[s][f], 132,
                                    wmma::mem_row_major);
    __syncthreads();

    if (rope) {
        // BN=128 covers 2 heads of 64; pair (i, i+32) within each head
        for (int i = tid; i < 128 * 16; i += 256) {
            int r  = i >> 4;
            int rest = i & 15;
            int hp = rest >> 3;
            int c  = hp * 64 + (rest & 7) * 4;   // within-head col base (0..28 step 4)
            int wcn = (rest & 7) * 4;            // rope table index base
            int sg = (bm + r) & (S_ - 1);
            float4 v1 = *(float4*)&Cs[r][c];
            float4 v2 = *(float4*)&Cs[r][c + 32];
            float4 cw = *(const float4*)(g_cos + sg * 32 + wcn);
            float4 sw = *(const float4*)(g_sin + sg * 32 + wcn);
            float4 b1 = *(const float4*)(bias + bn + c);
            float4 b2 = *(const float4*)(bias + bn + c + 32);
            float4 o1, o2;
            o1.x = v1.x * cw.x - v2.x * sw.x + b1.x;  o2.x = v2.x * cw.x + v1.x * sw.x + b2.x;
            o1.y = v1.y * cw.y - v2.y * sw.y + b1.y;  o2.y = v2.y * cw.y + v1.y * sw.y + b2.y;
            o1.z = v1.z * cw.z - v2.z * sw.z + b1.z;  o2.z = v2.z * cw.z + v1.z * sw.z + b2.z;
            o1.w = v1.w * cw.w - v2.w * sw.w + b1.w;  o2.w = v2.w * cw.w + v1.w * sw.w + b2.w;
            *(float4*)(C + (size_t)(bm + r) * N + bn + c)      = o1;
            *(float4*)(C + (size_t)(bm + r) * N + bn + c + 32) = o2;
        }
    } else {
        for (int i = tid; i < 128 * 32; i += 256) {
            int r = i >> 5;
            int c = (i & 31) * 4;
            float4 v  = *(float4*)&Cs[r][c];
            float4 bb = *(const float4*)(bias + bn + c);
            v.x += bb.x; v.y += bb.y; v.z += bb.z; v.w += bb.w;
            *(float4*)(C + (size_t)(bm + r) * N + bn + c) = v;
        }
    }
}

__global__ __launch_bounds__(256, 1) void qkv_kernel(
    const float* __restrict__ q, const float* __restrict__ k, const float* __restrict__ v,
    const float* __restrict__ Wq, const float* __restrict__ bq,
    const float* __restrict__ Wk, const float* __restrict__ bk,
    const float* __restrict__ Wv, const float* __restrict__ bv)
{
    extern __shared__ __align__(128) float sm[];
    float *Qp, *Kp, *Vp;
    Qp = g_Qp; Kp = g_Kp; Vp = g_Vp;
    if (blockIdx.z == 0)      gemm_body(q, Wq, bq, Qp, 1, sm);
    else if (blockIdx.z == 1) gemm_body(k, Wk, bk, Kp, 1, sm);
    else                      gemm_body(v, Wv, bv, Vp, 0, sm);
}

__global__ __launch_bounds__(256, 1) void oproj_kernel(
    const float* __restrict__ Wo, const float* __restrict__ bo, float* __restrict__ out)
{
    extern __shared__ __align__(128) float sm[];
    gemm_body(g_At, Wo, bo, out, 0, sm);
}

// ---------------------------------------------------------------------------
// Flash attention v3: 128-row Q tile, 64-row K/V tiles double-buffered,
// 8 warps (4x2). All operands tf32-pre-truncated; no fragment cvt.
// S aliases the Q smem region. 3 syncs per k-block.
// ---------------------------------------------------------------------------
#define FLD 68
#define F_QS 0
#define F_KS 8704
#define F_VS 17408
#define F_OA 26112
#define F_MR 34816
#define F_LR 34944
#define F_TOT 35072
#define F_KV1 4352        // one K or V buffer: 64*68

__global__ __launch_bounds__(256, 1) void flash_kernel()
{
    extern __shared__ __align__(128) float sm[];
    float (*QS)[FLD] = (float(*)[FLD])(sm + F_QS);   // Q, then S/P
    float (*OA)[FLD] = (float(*)[FLD])(sm + F_OA);
    float* mrow = sm + F_MR;
    float* lrow = sm + F_LR;

    const int qb = blockIdx.x, h = blockIdx.y, b = blockIdx.z;
    const int tid = threadIdx.x;
    const int wid = tid >> 5;
    const int wr  = wid >> 1;    // 0..3 -> rows wr*32
    const int wc  = wid & 1;     // 0..1 -> cols wc*32
    const int q0  = qb * 128;

    const float* Qg = g_Qp + ((size_t)b * S_ + q0) * D_ + h * DK_;
    const float* Kb = g_Kp + ((size_t)b * S_) * D_ + h * DK_;
    const float* Vb = g_Vp + ((size_t)b * S_) * D_ + h * DK_;

    // Prologue: Q (scaled+truncated), zero O, K0/V0
    for (int i = tid; i < 2048; i += 256) {
        int r = i >> 4, c = (i & 15) * 4;
        float4 v = *(const float4*)(Qg + (size_t)r * D_ + c);
        v.x *= 0.125f; v.y *= 0.125f; v.z *= 0.125f; v.w *= 0.125f;
        *(float4*)&QS[r][c] = tf32r4(v);
        *(float4*)&OA[r][c] = make_float4(0.f, 0.f, 0.f, 0.f);
    }
    for (int i = tid; i < 1024; i += 256) {
        int r = i >> 4, c = (i & 15) * 4;
        *(float4*)&sm[F_KS + r * FLD + c] = tf32r4(*(const float4*)(Kb + (size_t)r * D_ + c));
        *(float4*)&sm[F_VS + r * FLD + c] = tf32r4(*(const float4*)(Vb + (size_t)r * D_ + c));
    }
    if (tid < 128) { mrow[tid] = -1e30f; lrow[tid] = 0.0f; }
    __syncthreads();

    // Pre-extract Q fragments (already tf32)
    wmma::fragment<wmma::matrix_a, 16, 16, 8, wmma::precision::tf32, wmma::row_major> aq[2][8];
    #pragma unroll
    for (int s = 0; s < 2; s++)
        #pragma unroll
        for (int kk = 0; kk < 8; kk++)
            wmma::load_matrix_sync(aq[s][kk], &QS[wr * 32 + s * 16][kk * 8], FLD);
    __syncthreads();   // protect QS before first S-store

    const int nkb = 2 * qb + 2;
    const int lr  = tid >> 2;        // softmax row within half
    const int p   = tid & 3;

    for (int kb = 0; kb < nkb; kb++) {
        const int cur = kb & 1, nxt = cur ^ 1;

        // Stage next K/V tiles into registers (overlaps with S-MMA/softmax)
        float4 kst[4], vst[4];
        if (kb + 1 < nkb) {
            const float* Kg = Kb + (size_t)(kb + 1) * 64 * D_;
            const float* Vg = Vb + (size_t)(kb + 1) * 64 * D_;
            #pragma unroll
            for (int j = 0; j < 4; j++) {
                int i = tid + j * 256;
                int r = i >> 4, c = (i & 15) * 4;
                kst[j] = *(const float4*)(Kg + (size_t)r * D_ + c);
                vst[j] = *(const float4*)(Vg + (size_t)r * D_ + c);
            }
        }

        // S = Q @ K^T
        {
            wmma::fragment<wmma::accumulator, 16, 16, 8, float> sacc[2][2];
            #pragma unroll
            for (int s = 0; s < 2; s++)
                #pragma unroll
                for (int f = 0; f < 2; f++) wmma::fill_fragment(sacc[s][f], 0.0f);
            #pragma unroll
            for (int kk = 0; kk < 8; kk++) {
                wmma::fragment<wmma::matrix_b, 16, 16, 8, wmma::precision::tf32, wmma::col_major> bb[2];
                #pragma unroll
                for (int f = 0; f < 2; f++)
                    wmma::load_matrix_sync(bb[f],
                        &sm[F_KS + cur * F_KV1 + (wc * 32 + f * 16) * FLD + kk * 8], FLD);
                #pragma unroll
                for (int s = 0; s < 2; s++)
                    #pragma unroll
                    for (int f = 0; f < 2; f++)
                        wmma::mma_sync(sacc[s][f], aq[s][kk], bb[f], sacc[s][f]);
            }
            #pragma unroll
            for (int s = 0; s < 2; s++)
                #pragma unroll
                for (int f = 0; f < 2; f++)
                    wmma::store_matrix_sync(&QS[wr * 32 + s * 16][wc * 32 + f * 16], sacc[s][f],
                                            FLD, wmma::mem_row_major);
        }
        __syncthreads();

        // Online softmax + O rescale; P written tf32-truncated
        {
            const bool dz = (kb >= 2 * qb);
            #pragma unroll
            for (int half = 0; half < 2; half++) {
                int r = half * 64 + lr;
                float vals[16];
                float mx = -1e30f;
                #pragma unroll
                for (int j = 0; j < 16; j++) {
                    int c = p * 16 + j;
                    float sv = QS[r][c];
                    if (dz && kb * 64 + c > q0 + r) sv = -1e30f;
                    vals[j] = sv;
                    mx = fmaxf(mx, sv);
                }
                mx = fmaxf(mx, __shfl_xor_sync(0xffffffffu, mx, 1));
                mx = fmaxf(mx, __shfl_xor_sync(0xffffffffu, mx, 2));
                float mold = mrow[r];
                float mnew = fmaxf(mold, mx);
                float sum = 0.0f;
                #pragma unroll
                for (int j = 0; j < 16; j++) {
                    float pj = __expf(vals[j] - mnew);
                    QS[r][p * 16 + j] = tf32r(pj);
                    sum += pj;
                }
                sum += __shfl_xor_sync(0xffffffffu, sum, 1);
                sum += __shfl_xor_sync(0xffffffffu, sum, 2);
                float corr = __expf(mold - mnew);
                #pragma unroll
                for (int c4 = 0; c4 < 4; c4++) {
                    float4 v = *(float4*)&OA[r][p * 16 + c4 * 4];
                    v.x *= corr; v.y *= corr; v.z *= corr; v.w *= corr;
                    *(float4*)&OA[r][p * 16 + c4 * 4] = v;
                }
                if (p == 0) {
                    lrow[r] = lrow[r] * corr + sum;
                    mrow[r] = mnew;
                }
            }
        }

        // Store staged K/V into next buffers (safe: last read 2 syncs ago)
        if (kb + 1 < nkb) {
            #pragma unroll
            for (int j = 0; j < 4; j++) {
                int i = tid + j * 256;
                int r = i >> 4, c = (i & 15) * 4;
                *(float4*)&sm[F_KS + nxt * F_KV1 + r * FLD + c] = tf32r4(kst[j]);
                *(float4*)&sm[F_VS + nxt * F_KV1 + r * FLD + c] = tf32r4(vst[j]);
            }
        }
        __syncthreads();

        // O += P @ V
        {
            wmma::fragment<wmma::accumulator, 16, 16, 8, float> oacc[2][2];
            #pragma unroll
            for (int s = 0; s < 2; s++)
                #pragma unroll
                for (int f = 0; f < 2; f++)
                    wmma::load_matrix_sync(oacc[s][f], &OA[wr * 32 + s * 16][wc * 32 + f * 16],
                                           FLD, wmma::mem_row_major);
            #pragma unroll
            for (int kk = 0; kk < 8; kk++) {
                wmma::fragment<wmma::matrix_a, 16, 16, 8, wmma::precision::tf32, wmma::row_major> pa[2];
                wmma::fragment<wmma::matrix_b, 16, 16, 8, wmma::precision::tf32, wmma::row_major> vb[2];
                #pragma unroll
                for (int s = 0; s < 2; s++)
                    wmma::load_matrix_sync(pa[s], &QS[wr * 32 + s * 16][kk * 8], FLD);
                #pragma unroll
                for (int f = 0; f < 2; f++)
                    wmma::load_matrix_sync(vb[f],
                        &sm[F_VS + cur * F_KV1 + (kk * 8) * FLD + wc * 32 + f * 16], FLD);
                #pragma unroll
                for (int s = 0; s < 2; s++)
                    #pragma unroll
                    for (int f = 0; f < 2; f++)
                        wmma::mma_sync(oacc[s][f], pa[s], vb[f], oacc[s][f]);
            }
            #pragma unroll
            for (int s = 0; s < 2; s++)
                #pragma unroll
                for (int f = 0; f < 2; f++)
                    wmma::store_matrix_sync(&OA[wr * 32 + s * 16][wc * 32 + f * 16], oacc[s][f],
                                            FLD, wmma::mem_row_major);
        }
        __syncthreads();
    }

    // Epilogue: normalize and write g_At
    {
        float* Og = g_At + ((size_t)b * S_ + q0) * D_ + h * DK_;
        #pragma unroll
        for (int half = 0; half < 2; half++) {
            int r = half * 64 + lr;
            float inv_l = 1.0f / lrow[r];
            #pragma unroll
            for (int c4 = 0; c4 < 4; c4++) {
                float4 v = *(float4*)&OA[r][p * 16 + c4 * 4];
                v.x *= inv_l; v.y *= inv_l; v.z *= inv_l; v.w *= inv_l;
                *(float4*)(Og + (size_t)r * D_ + p * 16 + c4 * 4) = v;
            }
        }
    }
}

// ---------------------------------------------------------------------------
// Host launcher
// ---------------------------------------------------------------------------
extern "C" void kernel_launch(void* const* d_in, const int* in_sizes, int n_in,
                              void* d_out, int out_size)
{
    const float* q  = (const float*)d_in[0];
    const float* k  = (const float*)d_in[1];
    const float* v  = (const float*)d_in[2];
    const float* Wq = (const float*)d_in[4];
    const float* bq = (const float*)d_in[5];
    const float* Wk = (const float*)d_in[6];
    const float* bk = (const float*)d_in[7];
    const float* Wv = (const float*)d_in[8];
    const float* bv = (const float*)d_in[9];
    const float* Wo = (const float*)d_in[10];
    const float* bo = (const float*)d_in[11];
    float* out = (float*)d_out;

    table_kernel<<<S_ * 32 / 256, 256>>>();

    size_t gsmem = 128 * 132 * sizeof(float);   // 67.6 KB (epilogue alias)
    cudaFuncSetAttribute(qkv_kernel, cudaFuncAttributeMaxDynamicSharedMemorySize, (int)gsmem);
    cudaFuncSetAttribute(oproj_kernel, cudaFuncAttributeMaxDynamicSharedMemorySize, (int)gsmem);
    dim3 ggrid(1024 / 128, MTOT / 128, 3);   // (8, 32, 3)
    qkv_kernel<<<ggrid, 256, gsmem>>>(q, k, v, Wq, bq, Wk, bk, Wv, bv);

    size_t fsmem = F_TOT * sizeof(float);   // ~140.3 KB
    cudaFuncSetAttribute(flash_kernel, cudaFuncAttributeMaxDynamicSharedMemorySize, (int)fsmem);
    flash_kernel<<<dim3(S_ / 128, H_, B_), 256, fsmem>>>();

    oproj_kernel<<<dim3(8, 32), 256, gsmem>>>(Wo, bo, out);
}

// round 6
// speedup vs baseline: 1.4833x; 1.0306x over previous
#include <cuda_runtime.h>
#include <mma.h>
#include <math.h>
#include <stdint.h>

using namespace nvcuda;

#define B_   2
#define S_   2048
#define D_   1024
#define H_   16
#define DK_  64
#define MTOT (B_ * S_)   // 4096

__device__ float g_Qp[MTOT * D_];
__device__ float g_Kp[MTOT * D_];
__device__ float g_Vp[MTOT * D_];
__device__ float g_At[MTOT * D_];
__device__ float g_qr[MTOT * D_];
__device__ float g_kr[MTOT * D_];
__device__ float g_vr[MTOT * D_];
__device__ float g_Wt[4 * D_ * D_];     // transposed+rounded weights [N,K]
__device__ float g_cos[S_ * 32];
__device__ float g_sin[S_ * 32];

__device__ __forceinline__ float tf32r(float x) {
    float r;
    asm("cvt.rna.tf32.f32 %0, %1;" : "=f"(r) : "f"(x));
    return r;
}
__device__ __forceinline__ float4 tf32r4(float4 v) {
    v.x = tf32r(v.x); v.y = tf32r(v.y); v.z = tf32r(v.z); v.w = tf32r(v.w);
    return v;
}

__device__ __forceinline__ uint32_t smem_u32(const void* p) {
    uint32_t a;
    asm("{ .reg .u64 t; cvta.to.shared.u64 t, %1; cvt.u32.u64 %0, t; }" : "=r"(a) : "l"(p));
    return a;
}
__device__ __forceinline__ void cpa16(uint32_t dst, const void* src) {
    asm volatile("cp.async.cg.shared.global [%0], [%1], 16;" :: "r"(dst), "l"(src) : "memory");
}
#define CPA_COMMIT() asm volatile("cp.async.commit_group;" ::: "memory")
#define CPA_WAIT1()  asm volatile("cp.async.wait_group 1;" ::: "memory")
#define CPA_WAIT0()  asm volatile("cp.async.wait_group 0;" ::: "memory")

// ---------------------------------------------------------------------------
// Prep: RoPE tables, input rounding, weight transpose+round
// ---------------------------------------------------------------------------
__global__ void table_kernel()
{
    int idx = blockIdx.x * blockDim.x + threadIdx.x;   // 65536
    int i = idx & 31;
    int s = idx >> 5;
    double inv = exp(-((double)i / 32.0) * log(10000.0));
    double ang = (double)s * inv;
    g_cos[idx] = (float)cos(ang);
    g_sin[idx] = (float)sin(ang);
}

__global__ void round3_kernel(const float* __restrict__ q, const float* __restrict__ k,
                              const float* __restrict__ v)
{
    int i = blockIdx.x * blockDim.x + threadIdx.x;   // 1M float4 per array
    ((float4*)g_qr)[i] = tf32r4(((const float4*)q)[i]);
    ((float4*)g_kr)[i] = tf32r4(((const float4*)k)[i]);
    ((float4*)g_vr)[i] = tf32r4(((const float4*)v)[i]);
}

__global__ void transpose_kernel(const float* __restrict__ W0, const float* __restrict__ W1,
                                 const float* __restrict__ W2, const float* __restrict__ W3)
{
    __shared__ float t[32][33];
    const float* W = (blockIdx.z == 0) ? W0 : (blockIdx.z == 1) ? W1 : (blockIdx.z == 2) ? W2 : W3;
    float* Wt = g_Wt + (size_t)blockIdx.z * D_ * D_;
    int tx = threadIdx.x, ty = threadIdx.y;
    int x = blockIdx.x * 32 + tx;
    int y = blockIdx.y * 32 + ty;
    #pragma unroll
    for (int j = 0; j < 32; j += 8)
        t[ty + j][tx] = W[(size_t)(y + j) * D_ + x];
    __syncthreads();
    int x2 = blockIdx.y * 32 + tx;
    int y2 = blockIdx.x * 32 + ty;
    #pragma unroll
    for (int j = 0; j < 32; j += 8)
        Wt[(size_t)(y2 + j) * D_ + x2] = tf32r(t[tx][ty + j]);
}

// ---------------------------------------------------------------------------
// GEMM: C[128,128] tile = A[.,1024] @ Wt[.,1024]^T + bias (+RoPE, +round)
// cp.async double-buffered BK=32, 8 warps (2x4), warp tile 64x32, 2 CTA/SM.
// A and Wt are pre-rounded to tf32 in gmem; no cvt in the hot loop.
// ---------------------------------------------------------------------------
#define GST 36                   // stage row stride (floats)
#define G_A0 0
#define G_A1 4608
#define G_B0 9216
#define G_B1 13824
#define G_SM 18432               // stage total floats (73728 B)

__device__ __forceinline__ void gemm_body(
    const float* __restrict__ A, const float* __restrict__ Bt,
    const float* __restrict__ bias, float* __restrict__ C, int rope, int rnd)
{
    extern __shared__ __align__(128) float sm[];
    float (*Cs)[132] = (float(*)[132])sm;   // epilogue alias (128*132 <= G_SM)

    const int tid = threadIdx.x;
    const int wid = tid >> 5;
    const int wr  = wid >> 2;    // 0..1 -> rows wr*64
    const int wc  = wid & 3;     // 0..3 -> cols wc*32
    const int bm  = blockIdx.y * 128;
    const int bn  = blockIdx.x * 128;

    const uint32_t sb = smem_u32(sm);

    // Load geometry: 4 chunks per matrix per stage
    const int r0  = tid >> 3;       // rows r0, r0+32, r0+64, r0+96
    const int c4  = tid & 7;
    const float* Ag = A  + (size_t)(bm + r0) * D_ + c4 * 4;
    const float* Bg = Bt + (size_t)(bn + r0) * D_ + c4 * 4;
    uint32_t dstA[4], dstB[4];
    #pragma unroll
    for (int j = 0; j < 4; j++) {
        dstA[j] = sb + (uint32_t)((r0 + 32 * j) * GST + c4 * 4) * 4;
        dstB[j] = dstA[j] + G_B0 * 4;
    }

    wmma::fragment<wmma::accumulator, 16, 16, 8, float> acc[4][2];
    #pragma unroll
    for (int s = 0; s < 4; s++)
        #pragma unroll
        for (int f = 0; f < 2; f++) wmma::fill_fragment(acc[s][f], 0.0f);

    // Prologue: stage 0 -> buffer 0
    #pragma unroll
    for (int j = 0; j < 4; j++) {
        cpa16(dstA[j], Ag + (size_t)j * 32 * D_);
        cpa16(dstB[j], Bg + (size_t)j * 32 * D_);
    }
    CPA_COMMIT();

    for (int s = 0; s < 32; s++) {
        const int cur = s & 1;
        if (s < 31) {
            const uint32_t off = ((s + 1) & 1) ? G_A1 * 4 : 0;
            #pragma unroll
            for (int j = 0; j < 4; j++) {
                cpa16(dstA[j] + off, Ag + (size_t)j * 32 * D_ + (s + 1) * 32);
                cpa16(dstB[j] + off, Bg + (size_t)j * 32 * D_ + (s + 1) * 32);
            }
            CPA_COMMIT();
            CPA_WAIT1();
        } else {
            CPA_WAIT0();
        }
        __syncthreads();

        const float* As = sm + (cur ? G_A1 : G_A0);
        const float* Bs = sm + (cur ? G_B1 : G_B0);
        #pragma unroll
        for (int ks = 0; ks < 4; ks++) {
            wmma::fragment<wmma::matrix_a, 16, 16, 8, wmma::precision::tf32, wmma::row_major> a[4];
            wmma::fragment<wmma::matrix_b, 16, 16, 8, wmma::precision::tf32, wmma::col_major> bf[2];
            #pragma unroll
            for (int t = 0; t < 4; t++)
                wmma::load_matrix_sync(a[t], &As[(wr * 64 + t * 16) * GST + ks * 8], GST);
            #pragma unroll
            for (int f = 0; f < 2; f++)
                wmma::load_matrix_sync(bf[f], &Bs[(wc * 32 + f * 16) * GST + ks * 8], GST);
            #pragma unroll
            for (int t = 0; t < 4; t++)
                #pragma unroll
                for (int f = 0; f < 2; f++)
                    wmma::mma_sync(acc[t][f], a[t], bf[f], acc[t][f]);
        }
        __syncthreads();
    }

    // Epilogue
    #pragma unroll
    for (int t = 0; t < 4; t++)
        #pragma unroll
        for (int f = 0; f < 2; f++)
            wmma::store_matrix_sync(&Cs[wr * 64 + t * 16][wc * 32 + f * 16], acc[t][f], 132,
                                    wmma::mem_row_major);
    __syncthreads();

    if (rope) {
        // BN=128 covers 2 heads of 64; pair (i, i+32) within each head
        for (int i = tid; i < 128 * 16; i += 256) {
            int r  = i >> 4;
            int rest = i & 15;
            int hp = rest >> 3;
            int c  = hp * 64 + (rest & 7) * 4;
            int wcn = (rest & 7) * 4;
            int sg = (bm + r) & (S_ - 1);
            float4 v1 = *(float4*)&Cs[r][c];
            float4 v2 = *(float4*)&Cs[r][c + 32];
            float4 cw = *(const float4*)(g_cos + sg * 32 + wcn);
            float4 sw = *(const float4*)(g_sin + sg * 32 + wcn);
            float4 b1 = *(const float4*)(bias + bn + c);
            float4 b2 = *(const float4*)(bias + bn + c + 32);
            float4 o1, o2;
            o1.x = v1.x * cw.x - v2.x * sw.x + b1.x;  o2.x = v2.x * cw.x + v1.x * sw.x + b2.x;
            o1.y = v1.y * cw.y - v2.y * sw.y + b1.y;  o2.y = v2.y * cw.y + v1.y * sw.y + b2.y;
            o1.z = v1.z * cw.z - v2.z * sw.z + b1.z;  o2.z = v2.z * cw.z + v1.z * sw.z + b2.z;
            o1.w = v1.w * cw.w - v2.w * sw.w + b1.w;  o2.w = v2.w * cw.w + v1.w * sw.w + b2.w;
            *(float4*)(C + (size_t)(bm + r) * D_ + bn + c)      = tf32r4(o1);
            *(float4*)(C + (size_t)(bm + r) * D_ + bn + c + 32) = tf32r4(o2);
        }
    } else {
        for (int i = tid; i < 128 * 32; i += 256) {
            int r = i >> 5;
            int c = (i & 31) * 4;
            float4 v  = *(float4*)&Cs[r][c];
            float4 bb = *(const float4*)(bias + bn + c);
            v.x += bb.x; v.y += bb.y; v.z += bb.z; v.w += bb.w;
            if (rnd) v = tf32r4(v);
            *(float4*)(C + (size_t)(bm + r) * D_ + bn + c) = v;
        }
    }
}

__global__ __launch_bounds__(256, 2) void qkv_kernel(
    const float* __restrict__ bq, const float* __restrict__ bk, const float* __restrict__ bv)
{
    if (blockIdx.z == 0)      gemm_body(g_qr, g_Wt,               bq, g_Qp, 1, 1);
    else if (blockIdx.z == 1) gemm_body(g_kr, g_Wt + 1 * D_ * D_, bk, g_Kp, 1, 1);
    else                      gemm_body(g_vr, g_Wt + 2 * D_ * D_, bv, g_Vp, 0, 1);
}

__global__ __launch_bounds__(256, 2) void oproj_kernel(
    const float* __restrict__ bo, float* __restrict__ out)
{
    gemm_body(g_At, g_Wt + 3 * D_ * D_, bo, out, 0, 0);
}

// ---------------------------------------------------------------------------
// Flash attention: 512 threads (16 warps, 4x4), 128-row Q tile, 64-row K/V
// tiles cp.async double-buffered. All inputs pre-rounded tf32.
// ---------------------------------------------------------------------------
#define FLD 68
#define F_QS 0
#define F_K  8704
#define F_V  17408
#define F_OA 26112
#define F_MR 34816
#define F_LR 34944
#define F_TOT 35072
#define F_KV1 4352

__global__ __launch_bounds__(512, 1) void flash_kernel()
{
    extern __shared__ __align__(128) float sm[];
    float (*QS)[FLD] = (float(*)[FLD])(sm + F_QS);   // Q, then S/P
    float (*OA)[FLD] = (float(*)[FLD])(sm + F_OA);
    float* mrow = sm + F_MR;
    float* lrow = sm + F_LR;

    const int qb = blockIdx.x, h = blockIdx.y, b = blockIdx.z;
    const int tid = threadIdx.x;
    const int wid = tid >> 5;
    const int wr  = wid >> 2;    // 0..3 -> S rows wr*32
    const int wc  = wid & 3;     // 0..3 -> S cols wc*16
    const int q0  = qb * 128;

    const uint32_t sb = smem_u32(sm);
    const float* Qg = g_Qp + ((size_t)b * S_ + q0) * D_ + h * DK_;
    const float* Kb = g_Kp + ((size_t)b * S_) * D_ + h * DK_;
    const float* Vb = g_Vp + ((size_t)b * S_) * D_ + h * DK_;

    // Prologue: Q (x0.125, exact for tf32) + zero O + cp.async K0/V0
    #pragma unroll
    for (int j = 0; j < 4; j++) {
        int i = tid + j * 512;
        int r = i >> 4, c = (i & 15) * 4;
        float4 v = *(const float4*)(Qg + (size_t)r * D_ + c);
        v.x *= 0.125f; v.y *= 0.125f; v.z *= 0.125f; v.w *= 0.125f;
        *(float4*)&QS[r][c] = v;
        *(float4*)&OA[r][c] = make_float4(0.f, 0.f, 0.f, 0.f);
    }
    #pragma unroll
    for (int j = 0; j < 2; j++) {
        int i = tid + j * 512;
        int r = i >> 4, cc = i & 15;
        cpa16(sb + (F_K + r * FLD) * 4 + cc * 16, Kb + (size_t)r * D_ + cc * 4);
        cpa16(sb + (F_V + r * FLD) * 4 + cc * 16, Vb + (size_t)r * D_ + cc * 4);
    }
    CPA_COMMIT();
    if (tid < 128) { mrow[tid] = -1e30f; lrow[tid] = 0.0f; }
    CPA_WAIT0();
    __syncthreads();

    // Pre-extract Q fragments (invariant across kb)
    wmma::fragment<wmma::matrix_a, 16, 16, 8, wmma::precision::tf32, wmma::row_major> aq[2][8];
    #pragma unroll
    for (int s = 0; s < 2; s++)
        #pragma unroll
        for (int kk = 0; kk < 8; kk++)
            wmma::load_matrix_sync(aq[s][kk], &QS[wr * 32 + s * 16][kk * 8], FLD);
    __syncthreads();   // protect QS before first S-store

    const int nkb = 2 * qb + 2;
    const int lr  = tid >> 2;   // softmax row 0..127
    const int p   = tid & 3;

    for (int kb = 0; kb < nkb; kb++) {
        const int cur = kb & 1, nxt = cur ^ 1;

        // Issue next K/V tiles (async, other buffer)
        if (kb + 1 < nkb) {
            const float* Kg = Kb + (size_t)(kb + 1) * 64 * D_;
            const float* Vg = Vb + (size_t)(kb + 1) * 64 * D_;
            #pragma unroll
            for (int j = 0; j < 2; j++) {
                int i = tid + j * 512;
                int r = i >> 4, cc = i & 15;
                cpa16(sb + (F_K + nxt * F_KV1 + r * FLD) * 4 + cc * 16, Kg + (size_t)r * D_ + cc * 4);
                cpa16(sb + (F_V + nxt * F_KV1 + r * FLD) * 4 + cc * 16, Vg + (size_t)r * D_ + cc * 4);
            }
            CPA_COMMIT();
        }

        // S = Q @ K^T  (warp: rows wr*32+{0,16}, cols wc*16)
        {
            wmma::fragment<wmma::accumulator, 16, 16, 8, float> sacc[2];
            wmma::fill_fragment(sacc[0], 0.0f);
            wmma::fill_fragment(sacc[1], 0.0f);
            #pragma unroll
            for (int kk = 0; kk < 8; kk++) {
                wmma::fragment<wmma::matrix_b, 16, 16, 8, wmma::precision::tf32, wmma::col_major> bb;
                wmma::load_matrix_sync(bb, &sm[F_K + cur * F_KV1 + (wc * 16) * FLD + kk * 8], FLD);
                wmma::mma_sync(sacc[0], aq[0][kk], bb, sacc[0]);
                wmma::mma_sync(sacc[1], aq[1][kk], bb, sacc[1]);
            }
            wmma::store_matrix_sync(&QS[wr * 32][wc * 16],      sacc[0], FLD, wmma::mem_row_major);
            wmma::store_matrix_sync(&QS[wr * 32 + 16][wc * 16], sacc[1], FLD, wmma::mem_row_major);
        }
        __syncthreads();

        // Online softmax + O rescale (4 threads per row, all 128 rows)
        {
            const bool dz = (kb >= 2 * qb);
            float vals[16];
            float mx = -1e30f;
            #pragma unroll
            for (int j = 0; j < 16; j++) {
                int c = p * 16 + j;
                float sv = QS[lr][c];
                if (dz && kb * 64 + c > q0 + lr) sv = -1e30f;
                vals[j] = sv;
                mx = fmaxf(mx, sv);
            }
            mx = fmaxf(mx, __shfl_xor_sync(0xffffffffu, mx, 1));
            mx = fmaxf(mx, __shfl_xor_sync(0xffffffffu, mx, 2));
            float mold = mrow[lr];
            float mnew = fmaxf(mold, mx);
            float sum = 0.0f;
            #pragma unroll
            for (int j = 0; j < 16; j++) {
                float pj = __expf(vals[j] - mnew);
                QS[lr][p * 16 + j] = tf32r(pj);
                sum += pj;
            }
            sum += __shfl_xor_sync(0xffffffffu, sum, 1);
            sum += __shfl_xor_sync(0xffffffffu, sum, 2);
            float corr = __expf(mold - mnew);
            #pragma unroll
            for (int c4 = 0; c4 < 4; c4++) {
                float4 v = *(float4*)&OA[lr][p * 16 + c4 * 4];
                v.x *= corr; v.y *= corr; v.z *= corr; v.w *= corr;
                *(float4*)&OA[lr][p * 16 + c4 * 4] = v;
            }
            if (p == 0) {
                lrow[lr] = lrow[lr] * corr + sum;
                mrow[lr] = mnew;
            }
        }
        __syncthreads();

        // O += P @ V  (warp: rows wr*32+{0,16}, cols wc*16)
        {
            wmma::fragment<wmma::accumulator, 16, 16, 8, float> oacc[2];
            wmma::load_matrix_sync(oacc[0], &OA[wr * 32][wc * 16],      FLD, wmma::mem_row_major);
            wmma::load_matrix_sync(oacc[1], &OA[wr * 32 + 16][wc * 16], FLD, wmma::mem_row_major);
            #pragma unroll
            for (int kk = 0; kk < 8; kk++) {
                wmma::fragment<wmma::matrix_a, 16, 16, 8, wmma::precision::tf32, wmma::row_major> pa[2];
                wmma::fragment<wmma::matrix_b, 16, 16, 8, wmma::precision::tf32, wmma::row_major> vb;
                wmma::load_matrix_sync(pa[0], &QS[wr * 32][kk * 8],      FLD);
                wmma::load_matrix_sync(pa[1], &QS[wr * 32 + 16][kk * 8], FLD);
                wmma::load_matrix_sync(vb, &sm[F_V + cur * F_KV1 + (kk * 8) * FLD + wc * 16], FLD);
                wmma::mma_sync(oacc[0], pa[0], vb, oacc[0]);
                wmma::mma_sync(oacc[1], pa[1], vb, oacc[1]);
            }
            wmma::store_matrix_sync(&OA[wr * 32][wc * 16],      oacc[0], FLD, wmma::mem_row_major);
            wmma::store_matrix_sync(&OA[wr * 32 + 16][wc * 16], oacc[1], FLD, wmma::mem_row_major);
        }
        if (kb + 1 < nkb) CPA_WAIT0();
        __syncthreads();
    }

    // Epilogue: normalize, round to tf32 (feeds O-projection), write g_At
    {
        float inv_l = 1.0f / lrow[lr];
        float* Og = g_At + ((size_t)b * S_ + q0 + lr) * D_ + h * DK_;
        #pragma unroll
        for (int c4 = 0; c4 < 4; c4++) {
            float4 v = *(float4*)&OA[lr][p * 16 + c4 * 4];
            v.x *= inv_l; v.y *= inv_l; v.z *= inv_l; v.w *= inv_l;
            *(float4*)(Og + p * 16 + c4 * 4) = tf32r4(v);
        }
    }
}

// ---------------------------------------------------------------------------
// Host launcher
// ---------------------------------------------------------------------------
extern "C" void kernel_launch(void* const* d_in, const int* in_sizes, int n_in,
                              void* d_out, int out_size)
{
    const float* q  = (const float*)d_in[0];
    const float* k  = (const float*)d_in[1];
    const float* v  = (const float*)d_in[2];
    const float* Wq = (const float*)d_in[4];
    const float* bq = (const float*)d_in[5];
    const float* Wk = (const float*)d_in[6];
    const float* bk = (const float*)d_in[7];
    const float* Wv = (const float*)d_in[8];
    const float* bv = (const float*)d_in[9];
    const float* Wo = (const float*)d_in[10];
    const float* bo = (const float*)d_in[11];
    float* out = (float*)d_out;

    table_kernel<<<S_ * 32 / 256, 256>>>();
    round3_kernel<<<MTOT * D_ / 4 / 256, 256>>>(q, k, v);
    transpose_kernel<<<dim3(32, 32, 4), dim3(32, 8)>>>(Wq, Wk, Wv, Wo);

    size_t gsmem = G_SM * sizeof(float);   // 73728 B
    cudaFuncSetAttribute(qkv_kernel,   cudaFuncAttributeMaxDynamicSharedMemorySize, (int)gsmem);
    cudaFuncSetAttribute(oproj_kernel, cudaFuncAttributeMaxDynamicSharedMemorySize, (int)gsmem);
    qkv_kernel<<<dim3(8, 32, 3), 256, gsmem>>>(bq, bk, bv);

    size_t fsmem = F_TOT * sizeof(float);  // 140288 B
    cudaFuncSetAttribute(flash_kernel, cudaFuncAttributeMaxDynamicSharedMemorySize, (int)fsmem);
    flash_kernel<<<dim3(S_ / 128, H_, B_), 512, fsmem>>>();

    oproj_kernel<<<dim3(8, 32), 256, gsmem>>>(bo, out);
}

// round 7
// speedup vs baseline: 3.8565x; 2.5999x over previous
#include <cuda_runtime.h>
#include <mma.h>
#include <cuda_fp16.h>
#include <math.h>
#include <stdint.h>

using namespace nvcuda;

#define B_   2
#define S_   2048
#define D_   1024
#define H_   16
#define DK_  64
#define MTOT (B_ * S_)   // 4096

// fp16 staging buffers (allocation-free rule: __device__ globals)
__device__ __half g_qh[MTOT * D_];
__device__ __half g_kh[MTOT * D_];
__device__ __half g_vh[MTOT * D_];
__device__ __half g_Wh[4 * D_ * D_];    // transposed weights [N,K], fp16
__device__ __half g_Qh[MTOT * D_];      // projected Q (rope, x0.125)
__device__ __half g_Kh[MTOT * D_];      // projected K (rope)
__device__ __half g_Vh[MTOT * D_];      // projected V
__device__ __half g_Ath[MTOT * D_];     // attention output
__device__ float  g_cos[S_ * 32];
__device__ float  g_sin[S_ * 32];

__device__ __forceinline__ uint32_t smem_u32(const void* p) {
    uint32_t a;
    asm("{ .reg .u64 t; cvta.to.shared.u64 t, %1; cvt.u32.u64 %0, t; }" : "=r"(a) : "l"(p));
    return a;
}
__device__ __forceinline__ void cpa16(uint32_t dst, const void* src) {
    asm volatile("cp.async.cg.shared.global [%0], [%1], 16;" :: "r"(dst), "l"(src) : "memory");
}
#define CPA_COMMIT() asm volatile("cp.async.commit_group;" ::: "memory")
#define CPA_WAIT1()  asm volatile("cp.async.wait_group 1;" ::: "memory")
#define CPA_WAIT0()  asm volatile("cp.async.wait_group 0;" ::: "memory")

// ---------------------------------------------------------------------------
// Prep
// ---------------------------------------------------------------------------
__global__ void table_kernel()
{
    int idx = blockIdx.x * blockDim.x + threadIdx.x;   // 65536
    int i = idx & 31;
    int s = idx >> 5;
    double inv = exp(-((double)i / 32.0) * log(10000.0));
    double ang = (double)s * inv;
    g_cos[idx] = (float)cos(ang);
    g_sin[idx] = (float)sin(ang);
}

__global__ void tohalf3_kernel(const float* __restrict__ q, const float* __restrict__ k,
                               const float* __restrict__ v)
{
    int i = blockIdx.x * blockDim.x + threadIdx.x;   // 1M, 4 elems each
    float4 a = ((const float4*)q)[i];
    float4 b = ((const float4*)k)[i];
    float4 c = ((const float4*)v)[i];
    ((__half2*)g_qh)[i*2]   = __floats2half2_rn(a.x, a.y);
    ((__half2*)g_qh)[i*2+1] = __floats2half2_rn(a.z, a.w);
    ((__half2*)g_kh)[i*2]   = __floats2half2_rn(b.x, b.y);
    ((__half2*)g_kh)[i*2+1] = __floats2half2_rn(b.z, b.w);
    ((__half2*)g_vh)[i*2]   = __floats2half2_rn(c.x, c.y);
    ((__half2*)g_vh)[i*2+1] = __floats2half2_rn(c.z, c.w);
}

__global__ void transpose_kernel(const float* __restrict__ W0, const float* __restrict__ W1,
                                 const float* __restrict__ W2, const float* __restrict__ W3)
{
    __shared__ float t[32][33];
    const float* W = (blockIdx.z == 0) ? W0 : (blockIdx.z == 1) ? W1 : (blockIdx.z == 2) ? W2 : W3;
    __half* Wt = g_Wh + (size_t)blockIdx.z * D_ * D_;
    int tx = threadIdx.x, ty = threadIdx.y;
    int x = blockIdx.x * 32 + tx;
    int y = blockIdx.y * 32 + ty;
    #pragma unroll
    for (int j = 0; j < 32; j += 8)
        t[ty + j][tx] = W[(size_t)(y + j) * D_ + x];
    __syncthreads();
    int x2 = blockIdx.y * 32 + tx;
    int y2 = blockIdx.x * 32 + ty;
    #pragma unroll
    for (int j = 0; j < 32; j += 8)
        Wt[(size_t)(y2 + j) * D_ + x2] = __float2half_rn(t[tx][ty + j]);
}

// ---------------------------------------------------------------------------
// fp16 GEMM: C[128,128] tile = A[.,1024] @ Wt[.,1024]^T + bias (+RoPE)
// cp.async double-buffered BK=32, 8 warps (2x4), warp tile 64x32, 2 CTA/SM.
// ---------------------------------------------------------------------------
#define GST2 40                  // stage row stride (halves)
#define H_A1 5120                // halves
#define H_B0 10240
// stage total: 20480 halves = 40960 B; epilogue Cs fp32 128*132 = 67584 B

__device__ __forceinline__ void gemm_body(
    const __half* __restrict__ A, const __half* __restrict__ Bt,
    const float* __restrict__ bias, float* __restrict__ Cf, __half* __restrict__ Ch,
    int rope, float oscale)
{
    extern __shared__ __align__(128) char smc[];
    __half* smh = (__half*)smc;
    float (*Cs)[132] = (float(*)[132])smc;

    const int tid = threadIdx.x;
    const int wid = tid >> 5;
    const int wr  = wid >> 2;    // 0..1 -> rows wr*64
    const int wc  = wid & 3;     // 0..3 -> cols wc*32
    const int bm  = blockIdx.y * 128;
    const int bn  = blockIdx.x * 128;

    const uint32_t sb = smem_u32(smc);

    // Load geometry: 2 chunks (16B = 8 halves) per matrix per stage
    const int r0 = tid >> 2;     // rows r0, r0+64
    const int c8 = tid & 3;      // half-offset c8*8
    const __half* Ag = A  + (size_t)(bm + r0) * D_ + c8 * 8;
    const __half* Bg = Bt + (size_t)(bn + r0) * D_ + c8 * 8;
    uint32_t dstA[2], dstB[2];
    #pragma unroll
    for (int j = 0; j < 2; j++) {
        dstA[j] = sb + (uint32_t)((r0 + 64 * j) * GST2 + c8 * 8) * 2;
        dstB[j] = dstA[j] + H_B0 * 2;
    }

    wmma::fragment<wmma::accumulator, 16, 16, 16, float> acc[4][2];
    #pragma unroll
    for (int s = 0; s < 4; s++)
        #pragma unroll
        for (int f = 0; f < 2; f++) wmma::fill_fragment(acc[s][f], 0.0f);

    // Prologue
    #pragma unroll
    for (int j = 0; j < 2; j++) {
        cpa16(dstA[j], Ag + (size_t)j * 64 * D_);
        cpa16(dstB[j], Bg + (size_t)j * 64 * D_);
    }
    CPA_COMMIT();

    for (int s = 0; s < 32; s++) {
        const int cur = s & 1;
        if (s < 31) {
            const uint32_t off = ((s + 1) & 1) ? H_A1 * 2 : 0;
            #pragma unroll
            for (int j = 0; j < 2; j++) {
                cpa16(dstA[j] + off, Ag + (size_t)j * 64 * D_ + (s + 1) * 32);
                cpa16(dstB[j] + off, Bg + (size_t)j * 64 * D_ + (s + 1) * 32);
            }
            CPA_COMMIT();
            CPA_WAIT1();
        } else {
            CPA_WAIT0();
        }
        __syncthreads();

        const __half* As = smh + (cur ? H_A1 : 0);
        const __half* Bs = smh + H_B0 + (cur ? H_A1 : 0);
        #pragma unroll
        for (int ks = 0; ks < 2; ks++) {
            wmma::fragment<wmma::matrix_a, 16, 16, 16, __half, wmma::row_major> a[4];
            wmma::fragment<wmma::matrix_b, 16, 16, 16, __half, wmma::col_major> bf[2];
            #pragma unroll
            for (int t = 0; t < 4; t++)
                wmma::load_matrix_sync(a[t], &As[(wr * 64 + t * 16) * GST2 + ks * 16], GST2);
            #pragma unroll
            for (int f = 0; f < 2; f++)
                wmma::load_matrix_sync(bf[f], &Bs[(wc * 32 + f * 16) * GST2 + ks * 16], GST2);
            #pragma unroll
            for (int t = 0; t < 4; t++)
                #pragma unroll
                for (int f = 0; f < 2; f++)
                    wmma::mma_sync(acc[t][f], a[t], bf[f], acc[t][f]);
        }
        __syncthreads();
    }

    // Epilogue
    #pragma unroll
    for (int t = 0; t < 4; t++)
        #pragma unroll
        for (int f = 0; f < 2; f++)
            wmma::store_matrix_sync(&Cs[wr * 64 + t * 16][wc * 32 + f * 16], acc[t][f], 132,
                                    wmma::mem_row_major);
    __syncthreads();

    if (rope) {
        // BN=128 covers 2 heads of 64; pair (i, i+32) within each head; output fp16
        for (int i = tid; i < 128 * 16; i += 256) {
            int r  = i >> 4;
            int rest = i & 15;
            int hp = rest >> 3;
            int c  = hp * 64 + (rest & 7) * 4;
            int wcn = (rest & 7) * 4;
            int sg = (bm + r) & (S_ - 1);
            float4 v1 = *(float4*)&Cs[r][c];
            float4 v2 = *(float4*)&Cs[r][c + 32];
            float4 cw = *(const float4*)(g_cos + sg * 32 + wcn);
            float4 sw = *(const float4*)(g_sin + sg * 32 + wcn);
            float4 b1 = *(const float4*)(bias + bn + c);
            float4 b2 = *(const float4*)(bias + bn + c + 32);
            float4 o1, o2;
            o1.x = (v1.x * cw.x - v2.x * sw.x + b1.x) * oscale;
            o2.x = (v2.x * cw.x + v1.x * sw.x + b2.x) * oscale;
            o1.y = (v1.y * cw.y - v2.y * sw.y + b1.y) * oscale;
            o2.y = (v2.y * cw.y + v1.y * sw.y + b2.y) * oscale;
            o1.z = (v1.z * cw.z - v2.z * sw.z + b1.z) * oscale;
            o2.z = (v2.z * cw.z + v1.z * sw.z + b2.z) * oscale;
            o1.w = (v1.w * cw.w - v2.w * sw.w + b1.w) * oscale;
            o2.w = (v2.w * cw.w + v1.w * sw.w + b2.w) * oscale;
            __half* p1 = Ch + (size_t)(bm + r) * D_ + bn + c;
            __half* p2 = p1 + 32;
            *(__half2*)(p1)     = __floats2half2_rn(o1.x, o1.y);
            *(__half2*)(p1 + 2) = __floats2half2_rn(o1.z, o1.w);
            *(__half2*)(p2)     = __floats2half2_rn(o2.x, o2.y);
            *(__half2*)(p2 + 2) = __floats2half2_rn(o2.z, o2.w);
        }
    } else if (Ch) {
        for (int i = tid; i < 128 * 32; i += 256) {
            int r = i >> 5;
            int c = (i & 31) * 4;
            float4 v  = *(float4*)&Cs[r][c];
            float4 bb = *(const float4*)(bias + bn + c);
            v.x += bb.x; v.y += bb.y; v.z += bb.z; v.w += bb.w;
            __half* p = Ch + (size_t)(bm + r) * D_ + bn + c;
            *(__half2*)(p)     = __floats2half2_rn(v.x, v.y);
            *(__half2*)(p + 2) = __floats2half2_rn(v.z, v.w);
        }
    } else {
        for (int i = tid; i < 128 * 32; i += 256) {
            int r = i >> 5;
            int c = (i & 31) * 4;
            float4 v  = *(float4*)&Cs[r][c];
            float4 bb = *(const float4*)(bias + bn + c);
            v.x += bb.x; v.y += bb.y; v.z += bb.z; v.w += bb.w;
            *(float4*)(Cf + (size_t)(bm + r) * D_ + bn + c) = v;
        }
    }
}

__global__ __launch_bounds__(256, 2) void qkv_kernel(
    const float* __restrict__ bq, const float* __restrict__ bk, const float* __restrict__ bv)
{
    if (blockIdx.z == 0)      gemm_body(g_qh, g_Wh,               bq, nullptr, g_Qh, 1, 0.125f);
    else if (blockIdx.z == 1) gemm_body(g_kh, g_Wh + 1 * D_ * D_, bk, nullptr, g_Kh, 1, 1.0f);
    else                      gemm_body(g_vh, g_Wh + 2 * D_ * D_, bv, nullptr, g_Vh, 0, 1.0f);
}

__global__ __launch_bounds__(256, 2) void oproj_kernel(
    const float* __restrict__ bo, float* __restrict__ out)
{
    gemm_body(g_Ath, g_Wh + 3 * D_ * D_, bo, out, nullptr, 0, 1.0f);
}

// ---------------------------------------------------------------------------
// Flash attention fp16: 512 threads (16 warps, 4x4), 128-row Q tile,
// 64-row K/V tiles cp.async double-buffered. S/O accumulate fp32.
// ---------------------------------------------------------------------------
#define FB_QH 0          // 128*72 halves = 18432 B
#define FB_KH 18432      // 2 x 64*72 halves (9216 B each)
#define FB_VH 36864
#define FB_PH 55296      // 128*72 halves
#define FB_S  73728      // 128*68 fp32 = 34816 B
#define FB_OA 108544
#define FB_MR 143360
#define FB_LR 143872
#define FB_TOT 144384
#define KV_STRIDE_B 9216 // one K/V buffer in bytes

__global__ __launch_bounds__(512, 1) void flash_kernel()
{
    extern __shared__ __align__(128) char smc[];
    __half* QH = (__half*)(smc + FB_QH);      // [128][72]
    __half* KH = (__half*)(smc + FB_KH);
    __half* VH = (__half*)(smc + FB_VH);
    __half* PH = (__half*)(smc + FB_PH);      // [128][72]
    float (*Sf)[68] = (float(*)[68])(smc + FB_S);
    float (*OA)[68] = (float(*)[68])(smc + FB_OA);
    float* mrow = (float*)(smc + FB_MR);
    float* lrow = (float*)(smc + FB_LR);

    const int qb = blockIdx.x, h = blockIdx.y, b = blockIdx.z;
    const int tid = threadIdx.x;
    const int wid = tid >> 5;
    const int wr  = wid >> 2;    // 0..3 -> rows wr*32
    const int wc  = wid & 3;     // 0..3 -> cols wc*16
    const int q0  = qb * 128;

    const uint32_t sb = smem_u32(smc);
    const __half* Qg = g_Qh + ((size_t)b * S_ + q0) * D_ + h * DK_;
    const __half* Kb = g_Kh + ((size_t)b * S_) * D_ + h * DK_;
    const __half* Vb = g_Vh + ((size_t)b * S_) * D_ + h * DK_;

    // Prologue: cp.async Q (2 chunks/thread) + K0/V0 (1 chunk each)
    #pragma unroll
    for (int j = 0; j < 2; j++) {
        int i = tid + j * 512;             // 1024 chunks: r=i>>3, c8=i&7
        int r = i >> 3, c8 = i & 7;
        cpa16(sb + FB_QH + (uint32_t)(r * 72 + c8 * 8) * 2, Qg + (size_t)r * D_ + c8 * 8);
    }
    {
        int r = tid >> 3, c8 = tid & 7;    // 512 chunks each
        cpa16(sb + FB_KH + (uint32_t)(r * 72 + c8 * 8) * 2, Kb + (size_t)r * D_ + c8 * 8);
        cpa16(sb + FB_VH + (uint32_t)(r * 72 + c8 * 8) * 2, Vb + (size_t)r * D_ + c8 * 8);
    }
    CPA_COMMIT();
    for (int i = tid; i < 128 * 68; i += 512) ((float*)OA)[i] = 0.0f;
    if (tid < 128) { mrow[tid] = -1e30f; lrow[tid] = 0.0f; }
    CPA_WAIT0();
    __syncthreads();

    // Pre-extract Q fragments (QH never overwritten)
    wmma::fragment<wmma::matrix_a, 16, 16, 16, __half, wmma::row_major> aq[2][4];
    #pragma unroll
    for (int s = 0; s < 2; s++)
        #pragma unroll
        for (int kk = 0; kk < 4; kk++)
            wmma::load_matrix_sync(aq[s][kk], &QH[(wr * 32 + s * 16) * 72 + kk * 16], 72);

    const int nkb = 2 * qb + 2;
    const int lr  = tid >> 2;   // softmax row 0..127
    const int p   = tid & 3;

    for (int kb = 0; kb < nkb; kb++) {
        const int cur = kb & 1, nxt = cur ^ 1;

        // Issue next K/V tiles (async, other buffer)
        if (kb + 1 < nkb) {
            const __half* Kg = Kb + (size_t)(kb + 1) * 64 * D_;
            const __half* Vg = Vb + (size_t)(kb + 1) * 64 * D_;
            int r = tid >> 3, c8 = tid & 7;
            uint32_t o = (uint32_t)(nxt * KV_STRIDE_B + (r * 72 + c8 * 8) * 2);
            cpa16(sb + FB_KH + o, Kg + (size_t)r * D_ + c8 * 8);
            cpa16(sb + FB_VH + o, Vg + (size_t)r * D_ + c8 * 8);
            CPA_COMMIT();
        }

        // S = Q @ K^T
        {
            const __half* Kc = (__half*)((char*)KH + cur * KV_STRIDE_B);
            wmma::fragment<wmma::accumulator, 16, 16, 16, float> sacc[2];
            wmma::fill_fragment(sacc[0], 0.0f);
            wmma::fill_fragment(sacc[1], 0.0f);
            #pragma unroll
            for (int kk = 0; kk < 4; kk++) {
                wmma::fragment<wmma::matrix_b, 16, 16, 16, __half, wmma::col_major> bb;
                wmma::load_matrix_sync(bb, &Kc[(wc * 16) * 72 + kk * 16], 72);
                wmma::mma_sync(sacc[0], aq[0][kk], bb, sacc[0]);
                wmma::mma_sync(sacc[1], aq[1][kk], bb, sacc[1]);
            }
            wmma::store_matrix_sync(&Sf[wr * 32][wc * 16],      sacc[0], 68, wmma::mem_row_major);
            wmma::store_matrix_sync(&Sf[wr * 32 + 16][wc * 16], sacc[1], 68, wmma::mem_row_major);
        }
        __syncthreads();

        // Online softmax (fp32) + P->fp16 + O rescale
        {
            const bool dz = (kb >= 2 * qb);
            float vals[16];
            float mx = -1e30f;
            #pragma unroll
            for (int j = 0; j < 16; j++) {
                int c = p * 16 + j;
                float sv = Sf[lr][c];
                if (dz && kb * 64 + c > q0 + lr) sv = -1e30f;
                vals[j] = sv;
                mx = fmaxf(mx, sv);
            }
            mx = fmaxf(mx, __shfl_xor_sync(0xffffffffu, mx, 1));
            mx = fmaxf(mx, __shfl_xor_sync(0xffffffffu, mx, 2));
            float mold = mrow[lr];
            float mnew = fmaxf(mold, mx);
            float sum = 0.0f;
            #pragma unroll
            for (int j = 0; j < 16; j += 2) {
                float pj0 = __expf(vals[j]     - mnew);
                float pj1 = __expf(vals[j + 1] - mnew);
                *(__half2*)&PH[lr * 72 + p * 16 + j] = __floats2half2_rn(pj0, pj1);
                sum += pj0 + pj1;
            }
            sum += __shfl_xor_sync(0xffffffffu, sum, 1);
            sum += __shfl_xor_sync(0xffffffffu, sum, 2);
            float corr = __expf(mold - mnew);
            #pragma unroll
            for (int c4 = 0; c4 < 4; c4++) {
                float4 v = *(float4*)&OA[lr][p * 16 + c4 * 4];
                v.x *= corr; v.y *= corr; v.z *= corr; v.w *= corr;
                *(float4*)&OA[lr][p * 16 + c4 * 4] = v;
            }
            if (p == 0) {
                lrow[lr] = lrow[lr] * corr + sum;
                mrow[lr] = mnew;
            }
        }
        __syncthreads();

        // O += P @ V
        {
            const __half* Vc = (__half*)((char*)VH + cur * KV_STRIDE_B);
            wmma::fragment<wmma::accumulator, 16, 16, 16, float> oacc[2];
            wmma::load_matrix_sync(oacc[0], &OA[wr * 32][wc * 16],      68, wmma::mem_row_major);
            wmma::load_matrix_sync(oacc[1], &OA[wr * 32 + 16][wc * 16], 68, wmma::mem_row_major);
            #pragma unroll
            for (int kk = 0; kk < 4; kk++) {
                wmma::fragment<wmma::matrix_a, 16, 16, 16, __half, wmma::row_major> pa[2];
                wmma::fragment<wmma::matrix_b, 16, 16, 16, __half, wmma::row_major> vb;
                wmma::load_matrix_sync(pa[0], &PH[(wr * 32) * 72 + kk * 16],      72);
                wmma::load_matrix_sync(pa[1], &PH[(wr * 32 + 16) * 72 + kk * 16], 72);
                wmma::load_matrix_sync(vb, &Vc[(kk * 16) * 72 + wc * 16], 72);
                wmma::mma_sync(oacc[0], pa[0], vb, oacc[0]);
                wmma::mma_sync(oacc[1], pa[1], vb, oacc[1]);
            }
            wmma::store_matrix_sync(&OA[wr * 32][wc * 16],      oacc[0], 68, wmma::mem_row_major);
            wmma::store_matrix_sync(&OA[wr * 32 + 16][wc * 16], oacc[1], 68, wmma::mem_row_major);
        }
        if (kb + 1 < nkb) CPA_WAIT0();
        __syncthreads();
    }

    // Epilogue: normalize, convert to fp16, write g_Ath
    {
        float inv_l = 1.0f / lrow[lr];
        __half* Og = g_Ath + ((size_t)b * S_ + q0 + lr) * D_ + h * DK_ + p * 16;
        #pragma unroll
        for (int c4 = 0; c4 < 4; c4++) {
            float4 v = *(float4*)&OA[lr][p * 16 + c4 * 4];
            v.x *= inv_l; v.y *= inv_l; v.z *= inv_l; v.w *= inv_l;
            *(__half2*)(Og + c4 * 4)     = __floats2half2_rn(v.x, v.y);
            *(__half2*)(Og + c4 * 4 + 2) = __floats2half2_rn(v.z, v.w);
        }
    }
}

// ---------------------------------------------------------------------------
// Host launcher
// ---------------------------------------------------------------------------
extern "C" void kernel_launch(void* const* d_in, const int* in_sizes, int n_in,
                              void* d_out, int out_size)
{
    const float* q  = (const float*)d_in[0];
    const float* k  = (const float*)d_in[1];
    const float* v  = (const float*)d_in[2];
    const float* Wq = (const float*)d_in[4];
    const float* bq = (const float*)d_in[5];
    const float* Wk = (const float*)d_in[6];
    const float* bk = (const float*)d_in[7];
    const float* Wv = (const float*)d_in[8];
    const float* bv = (const float*)d_in[9];
    const float* Wo = (const float*)d_in[10];
    const float* bo = (const float*)d_in[11];
    float* out = (float*)d_out;

    table_kernel<<<S_ * 32 / 256, 256>>>();
    tohalf3_kernel<<<MTOT * D_ / 4 / 256, 256>>>(q, k, v);
    transpose_kernel<<<dim3(32, 32, 4), dim3(32, 8)>>>(Wq, Wk, Wv, Wo);

    size_t gsmem = 128 * 132 * sizeof(float);   // 67584 B (epilogue alias dominates)
    cudaFuncSetAttribute(qkv_kernel,   cudaFuncAttributeMaxDynamicSharedMemorySize, (int)gsmem);
    cudaFuncSetAttribute(oproj_kernel, cudaFuncAttributeMaxDynamicSharedMemorySize, (int)gsmem);
    qkv_kernel<<<dim3(8, 32, 3), 256, gsmem>>>(bq, bk, bv);

    size_t fsmem = FB_TOT;                      // 144384 B
    cudaFuncSetAttribute(flash_kernel, cudaFuncAttributeMaxDynamicSharedMemorySize, (int)fsmem);
    flash_kernel<<<dim3(S_ / 128, H_, B_), 512, fsmem>>>();

    oproj_kernel<<<dim3(8, 32), 256, gsmem>>>(bo, out);
}

// round 8
// speedup vs baseline: 5.7442x; 1.4895x over previous
#include <cuda_runtime.h>
#include <mma.h>
#include <cuda_fp16.h>
#include <math.h>
#include <stdint.h>

using namespace nvcuda;

#define B_   2
#define S_   2048
#define D_   1024
#define H_   16
#define DK_  64
#define MTOT (B_ * S_)   // 4096

__device__ __half g_qh[MTOT * D_];
__device__ __half g_kh[MTOT * D_];
__device__ __half g_vh[MTOT * D_];
__device__ __half g_Wh[4 * D_ * D_];    // transposed weights [N,K], fp16
__device__ __half g_Qh[MTOT * D_];      // projected Q (rope, x0.125)
__device__ __half g_Kh[MTOT * D_];      // projected K (rope)
__device__ __half g_Vh[MTOT * D_];      // projected V
__device__ __half g_Ath[MTOT * D_];     // attention output
__device__ float  g_cos[S_ * 32];
__device__ float  g_sin[S_ * 32];

__device__ __forceinline__ uint32_t smem_u32(const void* p) {
    uint32_t a;
    asm("{ .reg .u64 t; cvta.to.shared.u64 t, %1; cvt.u32.u64 %0, t; }" : "=r"(a) : "l"(p));
    return a;
}
__device__ __forceinline__ void cpa16(uint32_t dst, const void* src) {
    asm volatile("cp.async.cg.shared.global [%0], [%1], 16;" :: "r"(dst), "l"(src) : "memory");
}
#define CPA_COMMIT() asm volatile("cp.async.commit_group;" ::: "memory")
#define CPA_WAIT1()  asm volatile("cp.async.wait_group 1;" ::: "memory")
#define CPA_WAIT0()  asm volatile("cp.async.wait_group 0;" ::: "memory")

__device__ __forceinline__ void mma16816(float* c, const uint32_t* a, const uint32_t* b) {
    asm volatile("mma.sync.aligned.m16n8k16.row.col.f32.f16.f16.f32 "
        "{%0,%1,%2,%3}, {%4,%5,%6,%7}, {%8,%9}, {%0,%1,%2,%3};"
        : "+f"(c[0]), "+f"(c[1]), "+f"(c[2]), "+f"(c[3])
        : "r"(a[0]), "r"(a[1]), "r"(a[2]), "r"(a[3]), "r"(b[0]), "r"(b[1]));
}
__device__ __forceinline__ void ldsm4(uint32_t* r, uint32_t addr) {
    asm volatile("ldmatrix.sync.aligned.m8n8.x4.shared.b16 {%0,%1,%2,%3}, [%4];"
        : "=r"(r[0]), "=r"(r[1]), "=r"(r[2]), "=r"(r[3]) : "r"(addr));
}
__device__ __forceinline__ void ldsm4t(uint32_t* r, uint32_t addr) {
    asm volatile("ldmatrix.sync.aligned.m8n8.x4.trans.shared.b16 {%0,%1,%2,%3}, [%4];"
        : "=r"(r[0]), "=r"(r[1]), "=r"(r[2]), "=r"(r[3]) : "r"(addr));
}
__device__ __forceinline__ uint32_t h2u(float x, float y) {
    __half2 h = __floats2half2_rn(x, y);
    return *(uint32_t*)&h;
}

// ---------------------------------------------------------------------------
// Prep
// ---------------------------------------------------------------------------
__global__ void table_kernel()
{
    int idx = blockIdx.x * blockDim.x + threadIdx.x;   // 65536
    int i = idx & 31;
    int s = idx >> 5;
    double inv = exp(-((double)i / 32.0) * log(10000.0));
    double ang = (double)s * inv;
    g_cos[idx] = (float)cos(ang);
    g_sin[idx] = (float)sin(ang);
}

__global__ void tohalf3_kernel(const float* __restrict__ q, const float* __restrict__ k,
                               const float* __restrict__ v)
{
    int i = blockIdx.x * blockDim.x + threadIdx.x;
    float4 a = ((const float4*)q)[i];
    float4 b = ((const float4*)k)[i];
    float4 c = ((const float4*)v)[i];
    ((__half2*)g_qh)[i*2]   = __floats2half2_rn(a.x, a.y);
    ((__half2*)g_qh)[i*2+1] = __floats2half2_rn(a.z, a.w);
    ((__half2*)g_kh)[i*2]   = __floats2half2_rn(b.x, b.y);
    ((__half2*)g_kh)[i*2+1] = __floats2half2_rn(b.z, b.w);
    ((__half2*)g_vh)[i*2]   = __floats2half2_rn(c.x, c.y);
    ((__half2*)g_vh)[i*2+1] = __floats2half2_rn(c.z, c.w);
}

__global__ void transpose_kernel(const float* __restrict__ W0, const float* __restrict__ W1,
                                 const float* __restrict__ W2, const float* __restrict__ W3)
{
    __shared__ float t[32][33];
    const float* W = (blockIdx.z == 0) ? W0 : (blockIdx.z == 1) ? W1 : (blockIdx.z == 2) ? W2 : W3;
    __half* Wt = g_Wh + (size_t)blockIdx.z * D_ * D_;
    int tx = threadIdx.x, ty = threadIdx.y;
    int x = blockIdx.x * 32 + tx;
    int y = blockIdx.y * 32 + ty;
    #pragma unroll
    for (int j = 0; j < 32; j += 8)
        t[ty + j][tx] = W[(size_t)(y + j) * D_ + x];
    __syncthreads();
    int x2 = blockIdx.y * 32 + tx;
    int y2 = blockIdx.x * 32 + ty;
    #pragma unroll
    for (int j = 0; j < 32; j += 8)
        Wt[(size_t)(y2 + j) * D_ + x2] = __float2half_rn(t[tx][ty + j]);
}

// ---------------------------------------------------------------------------
// fp16 GEMM (unchanged from R7): 128x128 tile, BK=32, cp.async dbuf, 2 CTA/SM
// ---------------------------------------------------------------------------
#define GST2 40
#define H_A1 5120
#define H_B0 10240

__device__ __forceinline__ void gemm_body(
    const __half* __restrict__ A, const __half* __restrict__ Bt,
    const float* __restrict__ bias, float* __restrict__ Cf, __half* __restrict__ Ch,
    int rope, float oscale)
{
    extern __shared__ __align__(128) char smc[];
    __half* smh = (__half*)smc;
    float (*Cs)[132] = (float(*)[132])smc;

    const int tid = threadIdx.x;
    const int wid = tid >> 5;
    const int wr  = wid >> 2;
    const int wc  = wid & 3;
    const int bm  = blockIdx.y * 128;
    const int bn  = blockIdx.x * 128;

    const uint32_t sb = smem_u32(smc);

    const int r0 = tid >> 2;
    const int c8 = tid & 3;
    const __half* Ag = A  + (size_t)(bm + r0) * D_ + c8 * 8;
    const __half* Bg = Bt + (size_t)(bn + r0) * D_ + c8 * 8;
    uint32_t dstA[2], dstB[2];
    #pragma unroll
    for (int j = 0; j < 2; j++) {
        dstA[j] = sb + (uint32_t)((r0 + 64 * j) * GST2 + c8 * 8) * 2;
        dstB[j] = dstA[j] + H_B0 * 2;
    }

    wmma::fragment<wmma::accumulator, 16, 16, 16, float> acc[4][2];
    #pragma unroll
    for (int s = 0; s < 4; s++)
        #pragma unroll
        for (int f = 0; f < 2; f++) wmma::fill_fragment(acc[s][f], 0.0f);

    #pragma unroll
    for (int j = 0; j < 2; j++) {
        cpa16(dstA[j], Ag + (size_t)j * 64 * D_);
        cpa16(dstB[j], Bg + (size_t)j * 64 * D_);
    }
    CPA_COMMIT();

    for (int s = 0; s < 32; s++) {
        const int cur = s & 1;
        if (s < 31) {
            const uint32_t off = ((s + 1) & 1) ? H_A1 * 2 : 0;
            #pragma unroll
            for (int j = 0; j < 2; j++) {
                cpa16(dstA[j] + off, Ag + (size_t)j * 64 * D_ + (s + 1) * 32);
                cpa16(dstB[j] + off, Bg + (size_t)j * 64 * D_ + (s + 1) * 32);
            }
            CPA_COMMIT();
            CPA_WAIT1();
        } else {
            CPA_WAIT0();
        }
        __syncthreads();

        const __half* As = smh + (cur ? H_A1 : 0);
        const __half* Bs = smh + H_B0 + (cur ? H_A1 : 0);
        #pragma unroll
        for (int ks = 0; ks < 2; ks++) {
            wmma::fragment<wmma::matrix_a, 16, 16, 16, __half, wmma::row_major> a[4];
            wmma::fragment<wmma::matrix_b, 16, 16, 16, __half, wmma::col_major> bf[2];
            #pragma unroll
            for (int t = 0; t < 4; t++)
                wmma::load_matrix_sync(a[t], &As[(wr * 64 + t * 16) * GST2 + ks * 16], GST2);
            #pragma unroll
            for (int f = 0; f < 2; f++)
                wmma::load_matrix_sync(bf[f], &Bs[(wc * 32 + f * 16) * GST2 + ks * 16], GST2);
            #pragma unroll
            for (int t = 0; t < 4; t++)
                #pragma unroll
                for (int f = 0; f < 2; f++)
                    wmma::mma_sync(acc[t][f], a[t], bf[f], acc[t][f]);
        }
        __syncthreads();
    }

    #pragma unroll
    for (int t = 0; t < 4; t++)
        #pragma unroll
        for (int f = 0; f < 2; f++)
            wmma::store_matrix_sync(&Cs[wr * 64 + t * 16][wc * 32 + f * 16], acc[t][f], 132,
                                    wmma::mem_row_major);
    __syncthreads();

    if (rope) {
        for (int i = tid; i < 128 * 16; i += 256) {
            int r  = i >> 4;
            int rest = i & 15;
            int hp = rest >> 3;
            int c  = hp * 64 + (rest & 7) * 4;
            int wcn = (rest & 7) * 4;
            int sg = (bm + r) & (S_ - 1);
            float4 v1 = *(float4*)&Cs[r][c];
            float4 v2 = *(float4*)&Cs[r][c + 32];
            float4 cw = *(const float4*)(g_cos + sg * 32 + wcn);
            float4 sw = *(const float4*)(g_sin + sg * 32 + wcn);
            float4 b1 = *(const float4*)(bias + bn + c);
            float4 b2 = *(const float4*)(bias + bn + c + 32);
            float4 o1, o2;
            o1.x = (v1.x * cw.x - v2.x * sw.x + b1.x) * oscale;
            o2.x = (v2.x * cw.x + v1.x * sw.x + b2.x) * oscale;
            o1.y = (v1.y * cw.y - v2.y * sw.y + b1.y) * oscale;
            o2.y = (v2.y * cw.y + v1.y * sw.y + b2.y) * oscale;
            o1.z = (v1.z * cw.z - v2.z * sw.z + b1.z) * oscale;
            o2.z = (v2.z * cw.z + v1.z * sw.z + b2.z) * oscale;
            o1.w = (v1.w * cw.w - v2.w * sw.w + b1.w) * oscale;
            o2.w = (v2.w * cw.w + v1.w * sw.w + b2.w) * oscale;
            __half* p1 = Ch + (size_t)(bm + r) * D_ + bn + c;
            __half* p2 = p1 + 32;
            *(__half2*)(p1)     = __floats2half2_rn(o1.x, o1.y);
            *(__half2*)(p1 + 2) = __floats2half2_rn(o1.z, o1.w);
            *(__half2*)(p2)     = __floats2half2_rn(o2.x, o2.y);
            *(__half2*)(p2 + 2) = __floats2half2_rn(o2.z, o2.w);
        }
    } else if (Ch) {
        for (int i = tid; i < 128 * 32; i += 256) {
            int r = i >> 5;
            int c = (i & 31) * 4;
            float4 v  = *(float4*)&Cs[r][c];
            float4 bb = *(const float4*)(bias + bn + c);
            v.x += bb.x; v.y += bb.y; v.z += bb.z; v.w += bb.w;
            __half* p = Ch + (size_t)(bm + r) * D_ + bn + c;
            *(__half2*)(p)     = __floats2half2_rn(v.x, v.y);
            *(__half2*)(p + 2) = __floats2half2_rn(v.z, v.w);
        }
    } else {
        for (int i = tid; i < 128 * 32; i += 256) {
            int r = i >> 5;
            int c = (i & 31) * 4;
            float4 v  = *(float4*)&Cs[r][c];
            float4 bb = *(const float4*)(bias + bn + c);
            v.x += bb.x; v.y += bb.y; v.z += bb.z; v.w += bb.w;
            *(float4*)(Cf + (size_t)(bm + r) * D_ + bn + c) = v;
        }
    }
}

__global__ __launch_bounds__(256, 2) void qkv_kernel(
    const float* __restrict__ bq, const float* __restrict__ bk, const float* __restrict__ bv)
{
    if (blockIdx.z == 0)      gemm_body(g_qh, g_Wh,               bq, nullptr, g_Qh, 1, 0.125f);
    else if (blockIdx.z == 1) gemm_body(g_kh, g_Wh + 1 * D_ * D_, bk, nullptr, g_Kh, 1, 1.0f);
    else                      gemm_body(g_vh, g_Wh + 2 * D_ * D_, bv, nullptr, g_Vh, 0, 1.0f);
}

__global__ __launch_bounds__(256, 2) void oproj_kernel(
    const float* __restrict__ bo, float* __restrict__ out)
{
    gemm_body(g_Ath, g_Wh + 3 * D_ * D_, bo, out, nullptr, 0, 1.0f);
}

// ---------------------------------------------------------------------------
// Flash attention FA2-style: 256 threads (8 warps), each warp 16 q-rows.
// S/P/O/m/l in registers (mma.sync m16n8k16, documented layouts).
// K via ldmatrix, V via ldmatrix.trans. One sync per 64-col k-block.
// ---------------------------------------------------------------------------
#define FW_Q 0               // 128 x 72 halves = 18432 B
#define FW_K 18432           // 2 x (64 x 72) halves
#define FW_V 36864
#define FW_TOT 55296
#define KVS 9216             // one K/V buffer bytes

__global__ __launch_bounds__(256, 2) void flash_kernel()
{
    extern __shared__ __align__(128) char smc[];
    const int qb = blockIdx.x, h = blockIdx.y, b = blockIdx.z;
    const int tid  = threadIdx.x;
    const int w    = tid >> 5;
    const int lane = tid & 31;
    const int q0   = qb * 128;
    const int w16  = w * 16;

    const uint32_t sb = smem_u32(smc);
    const __half* Qg = g_Qh + ((size_t)b * S_ + q0) * D_ + h * DK_;
    const __half* Kb = g_Kh + ((size_t)b * S_) * D_ + h * DK_;
    const __half* Vb = g_Vh + ((size_t)b * S_) * D_ + h * DK_;

    // Prologue: cp.async Q (128x64) + K0/V0 (64x64 each)
    #pragma unroll
    for (int j = 0; j < 4; j++) {
        int i = tid + j * 256;
        int r = i >> 3, c8 = i & 7;
        cpa16(sb + FW_Q + (uint32_t)(r * 72 + c8 * 8) * 2, Qg + (size_t)r * D_ + c8 * 8);
    }
    #pragma unroll
    for (int j = 0; j < 2; j++) {
        int i = tid + j * 256;
        int r = i >> 3, c8 = i & 7;
        cpa16(sb + FW_K + (uint32_t)(r * 72 + c8 * 8) * 2, Kb + (size_t)r * D_ + c8 * 8);
        cpa16(sb + FW_V + (uint32_t)(r * 72 + c8 * 8) * 2, Vb + (size_t)r * D_ + c8 * 8);
    }
    CPA_COMMIT();
    CPA_WAIT0();
    __syncthreads();

    // Q A-fragments (4 k-chunks of 16)
    uint32_t aq[4][4];
    {
        uint32_t qa = sb + FW_Q +
            (uint32_t)((w16 + (lane & 15)) * 72 + ((lane & 16) ? 8 : 0)) * 2;
        #pragma unroll
        for (int kf = 0; kf < 4; kf++) ldsm4(aq[kf], qa + kf * 32);
    }

    float o[8][4];
    #pragma unroll
    for (int nf = 0; nf < 8; nf++) { o[nf][0]=0.f; o[nf][1]=0.f; o[nf][2]=0.f; o[nf][3]=0.f; }
    float m0 = -1e30f, m1 = -1e30f, l0 = 0.f, l1 = 0.f;

    const int nkb = 2 * qb + 2;
    const int rq0 = q0 + w16 + (lane >> 2);      // row of c0/c1; c2/c3 at rq0+8
    const int cc0 = (lane & 3) * 2;
    const uint32_t lmo = (uint32_t)((lane & 15) * 72 + ((lane & 16) ? 8 : 0)) * 2;

    for (int kb = 0; kb < nkb; kb++) {
        const int cur = kb & 1, nxt = cur ^ 1;

        if (kb + 1 < nkb) {
            const __half* Kg = Kb + (size_t)(kb + 1) * 64 * D_;
            const __half* Vg = Vb + (size_t)(kb + 1) * 64 * D_;
            #pragma unroll
            for (int j = 0; j < 2; j++) {
                int i = tid + j * 256;
                int r = i >> 3, c8 = i & 7;
                uint32_t off = (uint32_t)(nxt * KVS + (r * 72 + c8 * 8) * 2);
                cpa16(sb + FW_K + off, Kg + (size_t)r * D_ + c8 * 8);
                cpa16(sb + FW_V + off, Vg + (size_t)r * D_ + c8 * 8);
            }
            CPA_COMMIT();
        }

        // S = Q @ K^T  (8 n-frags of 8 cols)
        float s[8][4];
        #pragma unroll
        for (int nf = 0; nf < 8; nf++) { s[nf][0]=0.f; s[nf][1]=0.f; s[nf][2]=0.f; s[nf][3]=0.f; }
        {
            uint32_t ka = sb + FW_K + cur * KVS + lmo;
            #pragma unroll
            for (int kf = 0; kf < 4; kf++) {
                #pragma unroll
                for (int np = 0; np < 4; np++) {
                    uint32_t bk[4];
                    ldsm4(bk, ka + (uint32_t)(np * 16 * 72) * 2 + kf * 32);
                    uint32_t b0[2] = { bk[0], bk[2] };
                    uint32_t b1[2] = { bk[1], bk[3] };
                    mma16816(s[2*np],   aq[kf], b0);
                    mma16816(s[2*np+1], aq[kf], b1);
                }
            }
        }

        // Causal mask (register-level)
        if (kb >= 2 * qb) {
            #pragma unroll
            for (int nf = 0; nf < 8; nf++) {
                int c = kb * 64 + nf * 8 + cc0;
                if (c     > rq0)     s[nf][0] = -1e30f;
                if (c + 1 > rq0)     s[nf][1] = -1e30f;
                if (c     > rq0 + 8) s[nf][2] = -1e30f;
                if (c + 1 > rq0 + 8) s[nf][3] = -1e30f;
            }
        }

        // Online softmax in registers
        float mx0 = -1e30f, mx1 = -1e30f;
        #pragma unroll
        for (int nf = 0; nf < 8; nf++) {
            mx0 = fmaxf(mx0, fmaxf(s[nf][0], s[nf][1]));
            mx1 = fmaxf(mx1, fmaxf(s[nf][2], s[nf][3]));
        }
        mx0 = fmaxf(mx0, __shfl_xor_sync(0xffffffffu, mx0, 1));
        mx0 = fmaxf(mx0, __shfl_xor_sync(0xffffffffu, mx0, 2));
        mx1 = fmaxf(mx1, __shfl_xor_sync(0xffffffffu, mx1, 1));
        mx1 = fmaxf(mx1, __shfl_xor_sync(0xffffffffu, mx1, 2));
        float mn0 = fmaxf(m0, mx0), mn1 = fmaxf(m1, mx1);

        uint32_t pa[4][4];
        float sum0 = 0.f, sum1 = 0.f;
        #pragma unroll
        for (int np = 0; np < 4; np++) {
            float p00 = __expf(s[2*np][0]   - mn0), p01 = __expf(s[2*np][1]   - mn0);
            float p02 = __expf(s[2*np][2]   - mn1), p03 = __expf(s[2*np][3]   - mn1);
            float p10 = __expf(s[2*np+1][0] - mn0), p11 = __expf(s[2*np+1][1] - mn0);
            float p12 = __expf(s[2*np+1][2] - mn1), p13 = __expf(s[2*np+1][3] - mn1);
            sum0 += p00 + p01 + p10 + p11;
            sum1 += p02 + p03 + p12 + p13;
            pa[np][0] = h2u(p00, p01);
            pa[np][1] = h2u(p02, p03);
            pa[np][2] = h2u(p10, p11);
            pa[np][3] = h2u(p12, p13);
        }
        sum0 += __shfl_xor_sync(0xffffffffu, sum0, 1);
        sum0 += __shfl_xor_sync(0xffffffffu, sum0, 2);
        sum1 += __shfl_xor_sync(0xffffffffu, sum1, 1);
        sum1 += __shfl_xor_sync(0xffffffffu, sum1, 2);

        float c0 = __expf(m0 - mn0), c1 = __expf(m1 - mn1);
        l0 = l0 * c0 + sum0;
        l1 = l1 * c1 + sum1;
        m0 = mn0; m1 = mn1;
        #pragma unroll
        for (int nf = 0; nf < 8; nf++) {
            o[nf][0] *= c0; o[nf][1] *= c0; o[nf][2] *= c1; o[nf][3] *= c1;
        }

        // O += P @ V  (V via ldmatrix.trans)
        {
            uint32_t va = sb + FW_V + cur * KVS + lmo;
            #pragma unroll
            for (int kf = 0; kf < 4; kf++) {
                #pragma unroll
                for (int np = 0; np < 4; np++) {
                    uint32_t bv[4];
                    ldsm4t(bv, va + (uint32_t)(kf * 16 * 72) * 2 + np * 32);
                    uint32_t b0[2] = { bv[0], bv[1] };
                    uint32_t b1[2] = { bv[2], bv[3] };
                    mma16816(o[2*np],   pa[kf], b0);
                    mma16816(o[2*np+1], pa[kf], b1);
                }
            }
        }

        if (kb + 1 < nkb) CPA_WAIT0();
        __syncthreads();
    }

    // Epilogue: normalize, write fp16 to g_Ath
    {
        float il0 = 1.f / l0, il1 = 1.f / l1;
        __half* Og  = g_Ath + ((size_t)b * S_ + rq0) * D_ + h * DK_ + cc0;
        __half* Og8 = Og + 8 * D_;
        #pragma unroll
        for (int nf = 0; nf < 8; nf++) {
            *(__half2*)(Og  + nf * 8) = __floats2half2_rn(o[nf][0] * il0, o[nf][1] * il0);
            *(__half2*)(Og8 + nf * 8) = __floats2half2_rn(o[nf][2] * il1, o[nf][3] * il1);
        }
    }
}

// ---------------------------------------------------------------------------
// Host launcher
// ---------------------------------------------------------------------------
extern "C" void kernel_launch(void* const* d_in, const int* in_sizes, int n_in,
                              void* d_out, int out_size)
{
    const float* q  = (const float*)d_in[0];
    const float* k  = (const float*)d_in[1];
    const float* v  = (const float*)d_in[2];
    const float* Wq = (const float*)d_in[4];
    const float* bq = (const float*)d_in[5];
    const float* Wk = (const float*)d_in[6];
    const float* bk = (const float*)d_in[7];
    const float* Wv = (const float*)d_in[8];
    const float* bv = (const float*)d_in[9];
    const float* Wo = (const float*)d_in[10];
    const float* bo = (const float*)d_in[11];
    float* out = (float*)d_out;

    table_kernel<<<S_ * 32 / 256, 256>>>();
    tohalf3_kernel<<<MTOT * D_ / 4 / 256, 256>>>(q, k, v);
    transpose_kernel<<<dim3(32, 32, 4), dim3(32, 8)>>>(Wq, Wk, Wv, Wo);

    size_t gsmem = 128 * 132 * sizeof(float);   // 67584 B
    cudaFuncSetAttribute(qkv_kernel,   cudaFuncAttributeMaxDynamicSharedMemorySize, (int)gsmem);
    cudaFuncSetAttribute(oproj_kernel, cudaFuncAttributeMaxDynamicSharedMemorySize, (int)gsmem);
    qkv_kernel<<<dim3(8, 32, 3), 256, gsmem>>>(bq, bk, bv);

    size_t fsmem = FW_TOT;                      // 55296 B
    cudaFuncSetAttribute(flash_kernel, cudaFuncAttributeMaxDynamicSharedMemorySize, (int)fsmem);
    flash_kernel<<<dim3(S_ / 128, H_, B_), 256, fsmem>>>();

    oproj_kernel<<<dim3(8, 32), 256, gsmem>>>(bo, out);
}

// round 9
// speedup vs baseline: 6.8807x; 1.1978x over previous
#include <cuda_runtime.h>
#include <mma.h>
#include <cuda_fp16.h>
#include <math.h>
#include <stdint.h>

using namespace nvcuda;

#define B_   2
#define S_   2048
#define D_   1024
#define H_   16
#define DK_  64
#define MTOT (B_ * S_)   // 4096
#define LOG2E 1.44269504088896340736f

__device__ __half g_qh[MTOT * D_];
__device__ __half g_kh[MTOT * D_];
__device__ __half g_vh[MTOT * D_];
__device__ __half g_Wh[4 * D_ * D_];    // transposed weights [N,K], fp16
__device__ __half g_Qh[MTOT * D_];      // projected Q (rope, x 0.125*log2e)
__device__ __half g_Kh[MTOT * D_];      // projected K (rope)
__device__ __half g_Vh[MTOT * D_];      // projected V
__device__ __half g_Ath[MTOT * D_];     // attention output
__device__ float  g_cos[S_ * 32];
__device__ float  g_sin[S_ * 32];

__device__ __forceinline__ uint32_t smem_u32(const void* p) {
    uint32_t a;
    asm("{ .reg .u64 t; cvta.to.shared.u64 t, %1; cvt.u32.u64 %0, t; }" : "=r"(a) : "l"(p));
    return a;
}
__device__ __forceinline__ void cpa16(uint32_t dst, const void* src) {
    asm volatile("cp.async.cg.shared.global [%0], [%1], 16;" :: "r"(dst), "l"(src) : "memory");
}
#define CPA_COMMIT() asm volatile("cp.async.commit_group;" ::: "memory")
#define CPA_WAIT1()  asm volatile("cp.async.wait_group 1;" ::: "memory")
#define CPA_WAIT0()  asm volatile("cp.async.wait_group 0;" ::: "memory")

__device__ __forceinline__ void mma16816(float* c, const uint32_t* a, const uint32_t* b) {
    asm volatile("mma.sync.aligned.m16n8k16.row.col.f32.f16.f16.f32 "
        "{%0,%1,%2,%3}, {%4,%5,%6,%7}, {%8,%9}, {%0,%1,%2,%3};"
        : "+f"(c[0]), "+f"(c[1]), "+f"(c[2]), "+f"(c[3])
        : "r"(a[0]), "r"(a[1]), "r"(a[2]), "r"(a[3]), "r"(b[0]), "r"(b[1]));
}
__device__ __forceinline__ void ldsm4(uint32_t* r, uint32_t addr) {
    asm volatile("ldmatrix.sync.aligned.m8n8.x4.shared.b16 {%0,%1,%2,%3}, [%4];"
        : "=r"(r[0]), "=r"(r[1]), "=r"(r[2]), "=r"(r[3]) : "r"(addr));
}
__device__ __forceinline__ void ldsm4t(uint32_t* r, uint32_t addr) {
    asm volatile("ldmatrix.sync.aligned.m8n8.x4.trans.shared.b16 {%0,%1,%2,%3}, [%4];"
        : "=r"(r[0]), "=r"(r[1]), "=r"(r[2]), "=r"(r[3]) : "r"(addr));
}
__device__ __forceinline__ uint32_t h2u(float x, float y) {
    __half2 h = __floats2half2_rn(x, y);
    return *(uint32_t*)&h;
}

// ---------------------------------------------------------------------------
// Prep
// ---------------------------------------------------------------------------
__global__ void table_kernel()
{
    int idx = blockIdx.x * blockDim.x + threadIdx.x;   // 65536
    int i = idx & 31;
    int s = idx >> 5;
    double inv = exp(-((double)i / 32.0) * log(10000.0));
    double ang = (double)s * inv;
    g_cos[idx] = (float)cos(ang);
    g_sin[idx] = (float)sin(ang);
}

__global__ void tohalf3_kernel(const float* __restrict__ q, const float* __restrict__ k,
                               const float* __restrict__ v)
{
    int i = blockIdx.x * blockDim.x + threadIdx.x;
    float4 a = ((const float4*)q)[i];
    float4 b = ((const float4*)k)[i];
    float4 c = ((const float4*)v)[i];
    ((__half2*)g_qh)[i*2]   = __floats2half2_rn(a.x, a.y);
    ((__half2*)g_qh)[i*2+1] = __floats2half2_rn(a.z, a.w);
    ((__half2*)g_kh)[i*2]   = __floats2half2_rn(b.x, b.y);
    ((__half2*)g_kh)[i*2+1] = __floats2half2_rn(b.z, b.w);
    ((__half2*)g_vh)[i*2]   = __floats2half2_rn(c.x, c.y);
    ((__half2*)g_vh)[i*2+1] = __floats2half2_rn(c.z, c.w);
}

__global__ void transpose_kernel(const float* __restrict__ W0, const float* __restrict__ W1,
                                 const float* __restrict__ W2, const float* __restrict__ W3)
{
    __shared__ float t[32][33];
    const float* W = (blockIdx.z == 0) ? W0 : (blockIdx.z == 1) ? W1 : (blockIdx.z == 2) ? W2 : W3;
    __half* Wt = g_Wh + (size_t)blockIdx.z * D_ * D_;
    int tx = threadIdx.x, ty = threadIdx.y;
    int x = blockIdx.x * 32 + tx;
    int y = blockIdx.y * 32 + ty;
    #pragma unroll
    for (int j = 0; j < 32; j += 8)
        t[ty + j][tx] = W[(size_t)(y + j) * D_ + x];
    __syncthreads();
    int x2 = blockIdx.y * 32 + tx;
    int y2 = blockIdx.x * 32 + ty;
    #pragma unroll
    for (int j = 0; j < 32; j += 8)
        Wt[(size_t)(y2 + j) * D_ + x2] = __float2half_rn(t[tx][ty + j]);
}

// ---------------------------------------------------------------------------
// fp16 GEMM: 128x128 tile, BK=64 (16 stages), cp.async dbuf, 2 CTA/SM.
// smem: A[128][72] + B[128][72] per buffer (18432 B each), 73728 B total.
// ---------------------------------------------------------------------------
#define GLD 72                   // stage row stride (halves)
#define GBUF 9216                // one matrix buffer (halves)

__device__ __forceinline__ void gemm_body(
    const __half* __restrict__ A, const __half* __restrict__ Bt,
    const float* __restrict__ bias, float* __restrict__ Cf, __half* __restrict__ Ch,
    int rope, float oscale)
{
    extern __shared__ __align__(128) char smc[];
    __half* smh = (__half*)smc;
    float (*Cs)[132] = (float(*)[132])smc;

    const int tid = threadIdx.x;
    const int wid = tid >> 5;
    const int wr  = wid >> 2;    // 0..1 -> rows wr*64
    const int wc  = wid & 3;     // 0..3 -> cols wc*32
    const int bm  = blockIdx.y * 128;
    const int bn  = blockIdx.x * 128;

    const uint32_t sb = smem_u32(smc);

    // Load geometry: 4 chunks (16B) per matrix per stage
    const int r0 = tid >> 3;     // rows r0 + 32j
    const int c8 = tid & 7;
    const __half* Ag = A  + (size_t)(bm + r0) * D_ + c8 * 8;
    const __half* Bg = Bt + (size_t)(bn + r0) * D_ + c8 * 8;
    uint32_t dstA[4], dstB[4];
    #pragma unroll
    for (int j = 0; j < 4; j++) {
        dstA[j] = sb + (uint32_t)((r0 + 32 * j) * GLD + c8 * 8) * 2;
        dstB[j] = dstA[j] + GBUF * 2;
    }

    wmma::fragment<wmma::accumulator, 16, 16, 16, float> acc[4][2];
    #pragma unroll
    for (int s = 0; s < 4; s++)
        #pragma unroll
        for (int f = 0; f < 2; f++) wmma::fill_fragment(acc[s][f], 0.0f);

    // Prologue: stage 0 -> buffer 0
    #pragma unroll
    for (int j = 0; j < 4; j++) {
        cpa16(dstA[j], Ag + (size_t)(r0 ? 0 : 0) + (size_t)j * 32 * D_);
        cpa16(dstB[j], Bg + (size_t)j * 32 * D_);
    }
    CPA_COMMIT();

    for (int s = 0; s < 16; s++) {
        const int cur = s & 1;
        if (s < 15) {
            const uint32_t off = ((s + 1) & 1) ? 2 * GBUF * 2 : 0;
            #pragma unroll
            for (int j = 0; j < 4; j++) {
                cpa16(dstA[j] + off, Ag + (size_t)j * 32 * D_ + (s + 1) * 64);
                cpa16(dstB[j] + off, Bg + (size_t)j * 32 * D_ + (s + 1) * 64);
            }
            CPA_COMMIT();
            CPA_WAIT1();
        } else {
            CPA_WAIT0();
        }
        __syncthreads();

        const __half* As = smh + (cur ? 2 * GBUF : 0);
        const __half* Bs = As + GBUF;
        #pragma unroll
        for (int ks = 0; ks < 4; ks++) {
            wmma::fragment<wmma::matrix_a, 16, 16, 16, __half, wmma::row_major> a[4];
            wmma::fragment<wmma::matrix_b, 16, 16, 16, __half, wmma::col_major> bf[2];
            #pragma unroll
            for (int t = 0; t < 4; t++)
                wmma::load_matrix_sync(a[t], &As[(wr * 64 + t * 16) * GLD + ks * 16], GLD);
            #pragma unroll
            for (int f = 0; f < 2; f++)
                wmma::load_matrix_sync(bf[f], &Bs[(wc * 32 + f * 16) * GLD + ks * 16], GLD);
            #pragma unroll
            for (int t = 0; t < 4; t++)
                #pragma unroll
                for (int f = 0; f < 2; f++)
                    wmma::mma_sync(acc[t][f], a[t], bf[f], acc[t][f]);
        }
        __syncthreads();
    }

    // Epilogue
    #pragma unroll
    for (int t = 0; t < 4; t++)
        #pragma unroll
        for (int f = 0; f < 2; f++)
            wmma::store_matrix_sync(&Cs[wr * 64 + t * 16][wc * 32 + f * 16], acc[t][f], 132,
                                    wmma::mem_row_major);
    __syncthreads();

    if (rope) {
        for (int i = tid; i < 128 * 16; i += 256) {
            int r  = i >> 4;
            int rest = i & 15;
            int hp = rest >> 3;
            int c  = hp * 64 + (rest & 7) * 4;
            int wcn = (rest & 7) * 4;
            int sg = (bm + r) & (S_ - 1);
            float4 v1 = *(float4*)&Cs[r][c];
            float4 v2 = *(float4*)&Cs[r][c + 32];
            float4 cw = *(const float4*)(g_cos + sg * 32 + wcn);
            float4 sw = *(const float4*)(g_sin + sg * 32 + wcn);
            float4 b1 = *(const float4*)(bias + bn + c);
            float4 b2 = *(const float4*)(bias + bn + c + 32);
            float4 o1, o2;
            o1.x = (v1.x * cw.x - v2.x * sw.x + b1.x) * oscale;
            o2.x = (v2.x * cw.x + v1.x * sw.x + b2.x) * oscale;
            o1.y = (v1.y * cw.y - v2.y * sw.y + b1.y) * oscale;
            o2.y = (v2.y * cw.y + v1.y * sw.y + b2.y) * oscale;
            o1.z = (v1.z * cw.z - v2.z * sw.z + b1.z) * oscale;
            o2.z = (v2.z * cw.z + v1.z * sw.z + b2.z) * oscale;
            o1.w = (v1.w * cw.w - v2.w * sw.w + b1.w) * oscale;
            o2.w = (v2.w * cw.w + v1.w * sw.w + b2.w) * oscale;
            __half* p1 = Ch + (size_t)(bm + r) * D_ + bn + c;
            __half* p2 = p1 + 32;
            *(__half2*)(p1)     = __floats2half2_rn(o1.x, o1.y);
            *(__half2*)(p1 + 2) = __floats2half2_rn(o1.z, o1.w);
            *(__half2*)(p2)     = __floats2half2_rn(o2.x, o2.y);
            *(__half2*)(p2 + 2) = __floats2half2_rn(o2.z, o2.w);
        }
    } else if (Ch) {
        for (int i = tid; i < 128 * 32; i += 256) {
            int r = i >> 5;
            int c = (i & 31) * 4;
            float4 v  = *(float4*)&Cs[r][c];
            float4 bb = *(const float4*)(bias + bn + c);
            v.x += bb.x; v.y += bb.y; v.z += bb.z; v.w += bb.w;
            __half* p = Ch + (size_t)(bm + r) * D_ + bn + c;
            *(__half2*)(p)     = __floats2half2_rn(v.x, v.y);
            *(__half2*)(p + 2) = __floats2half2_rn(v.z, v.w);
        }
    } else {
        for (int i = tid; i < 128 * 32; i += 256) {
            int r = i >> 5;
            int c = (i & 31) * 4;
            float4 v  = *(float4*)&Cs[r][c];
            float4 bb = *(const float4*)(bias + bn + c);
            v.x += bb.x; v.y += bb.y; v.z += bb.z; v.w += bb.w;
            *(float4*)(Cf + (size_t)(bm + r) * D_ + bn + c) = v;
        }
    }
}

__global__ __launch_bounds__(256, 2) void qkv_kernel(
    const float* __restrict__ bq, const float* __restrict__ bk, const float* __restrict__ bv)
{
    if (blockIdx.z == 0)      gemm_body(g_qh, g_Wh,               bq, nullptr, g_Qh, 1, 0.125f * LOG2E);
    else if (blockIdx.z == 1) gemm_body(g_kh, g_Wh + 1 * D_ * D_, bk, nullptr, g_Kh, 1, 1.0f);
    else                      gemm_body(g_vh, g_Wh + 2 * D_ * D_, bv, nullptr, g_Vh, 0, 1.0f);
}

__global__ __launch_bounds__(256, 2) void oproj_kernel(
    const float* __restrict__ bo, float* __restrict__ out)
{
    gemm_body(g_Ath, g_Wh + 3 * D_ * D_, bo, out, nullptr, 0, 1.0f);
}

// ---------------------------------------------------------------------------
// Flash attention FA2 (registers), base-2 softmax, LPT-ordered 1D grid.
// ---------------------------------------------------------------------------
#define FW_Q 0               // 128 x 72 halves = 18432 B
#define FW_K 18432           // 2 x (64 x 72) halves
#define FW_V 36864
#define FW_TOT 55296
#define KVS 9216             // one K/V buffer bytes

__global__ __launch_bounds__(256, 2) void flash_kernel()
{
    extern __shared__ __align__(128) char smc[];
    // LPT: heavy (high-qb) CTAs first
    const int idx = blockIdx.x;
    const int qb = 15 - (idx >> 5);
    const int h  = idx & 15;
    const int b  = (idx >> 4) & 1;

    const int tid  = threadIdx.x;
    const int w    = tid >> 5;
    const int lane = tid & 31;
    const int q0   = qb * 128;
    const int w16  = w * 16;

    const uint32_t sb = smem_u32(smc);
    const __half* Qg = g_Qh + ((size_t)b * S_ + q0) * D_ + h * DK_;
    const __half* Kb = g_Kh + ((size_t)b * S_) * D_ + h * DK_;
    const __half* Vb = g_Vh + ((size_t)b * S_) * D_ + h * DK_;

    #pragma unroll
    for (int j = 0; j < 4; j++) {
        int i = tid + j * 256;
        int r = i >> 3, c8 = i & 7;
        cpa16(sb + FW_Q + (uint32_t)(r * 72 + c8 * 8) * 2, Qg + (size_t)r * D_ + c8 * 8);
    }
    #pragma unroll
    for (int j = 0; j < 2; j++) {
        int i = tid + j * 256;
        int r = i >> 3, c8 = i & 7;
        cpa16(sb + FW_K + (uint32_t)(r * 72 + c8 * 8) * 2, Kb + (size_t)r * D_ + c8 * 8);
        cpa16(sb + FW_V + (uint32_t)(r * 72 + c8 * 8) * 2, Vb + (size_t)r * D_ + c8 * 8);
    }
    CPA_COMMIT();
    CPA_WAIT0();
    __syncthreads();

    uint32_t aq[4][4];
    {
        uint32_t qa = sb + FW_Q +
            (uint32_t)((w16 + (lane & 15)) * 72 + ((lane & 16) ? 8 : 0)) * 2;
        #pragma unroll
        for (int kf = 0; kf < 4; kf++) ldsm4(aq[kf], qa + kf * 32);
    }

    float o[8][4];
    #pragma unroll
    for (int nf = 0; nf < 8; nf++) { o[nf][0]=0.f; o[nf][1]=0.f; o[nf][2]=0.f; o[nf][3]=0.f; }
    float m0 = -1e30f, m1 = -1e30f, l0 = 0.f, l1 = 0.f;

    const int nkb = 2 * qb + 2;
    const int rq0 = q0 + w16 + (lane >> 2);
    const int cc0 = (lane & 3) * 2;
    const uint32_t lmo = (uint32_t)((lane & 15) * 72 + ((lane & 16) ? 8 : 0)) * 2;

    for (int kb = 0; kb < nkb; kb++) {
        const int cur = kb & 1, nxt = cur ^ 1;

        if (kb + 1 < nkb) {
            const __half* Kg = Kb + (size_t)(kb + 1) * 64 * D_;
            const __half* Vg = Vb + (size_t)(kb + 1) * 64 * D_;
            #pragma unroll
            for (int j = 0; j < 2; j++) {
                int i = tid + j * 256;
                int r = i >> 3, c8 = i & 7;
                uint32_t off = (uint32_t)(nxt * KVS + (r * 72 + c8 * 8) * 2);
                cpa16(sb + FW_K + off, Kg + (size_t)r * D_ + c8 * 8);
                cpa16(sb + FW_V + off, Vg + (size_t)r * D_ + c8 * 8);
            }
            CPA_COMMIT();
        }

        // S = Q @ K^T (logits already scaled by log2e/8 via Q projection)
        float s[8][4];
        #pragma unroll
        for (int nf = 0; nf < 8; nf++) { s[nf][0]=0.f; s[nf][1]=0.f; s[nf][2]=0.f; s[nf][3]=0.f; }
        {
            uint32_t ka = sb + FW_K + cur * KVS + lmo;
            #pragma unroll
            for (int kf = 0; kf < 4; kf++) {
                #pragma unroll
                for (int np = 0; np < 4; np++) {
                    uint32_t bk[4];
                    ldsm4(bk, ka + (uint32_t)(np * 16 * 72) * 2 + kf * 32);
                    uint32_t b0[2] = { bk[0], bk[2] };
                    uint32_t b1[2] = { bk[1], bk[3] };
                    mma16816(s[2*np],   aq[kf], b0);
                    mma16816(s[2*np+1], aq[kf], b1);
                }
            }
        }

        if (kb >= 2 * qb) {
            #pragma unroll
            for (int nf = 0; nf < 8; nf++) {
                int c = kb * 64 + nf * 8 + cc0;
                if (c     > rq0)     s[nf][0] = -1e30f;
                if (c + 1 > rq0)     s[nf][1] = -1e30f;
                if (c     > rq0 + 8) s[nf][2] = -1e30f;
                if (c + 1 > rq0 + 8) s[nf][3] = -1e30f;
            }
        }

        float mx0 = -1e30f, mx1 = -1e30f;
        #pragma unroll
        for (int nf = 0; nf < 8; nf++) {
            mx0 = fmaxf(mx0, fmaxf(s[nf][0], s[nf][1]));
            mx1 = fmaxf(mx1, fmaxf(s[nf][2], s[nf][3]));
        }
        mx0 = fmaxf(mx0, __shfl_xor_sync(0xffffffffu, mx0, 1));
        mx0 = fmaxf(mx0, __shfl_xor_sync(0xffffffffu, mx0, 2));
        mx1 = fmaxf(mx1, __shfl_xor_sync(0xffffffffu, mx1, 1));
        mx1 = fmaxf(mx1, __shfl_xor_sync(0xffffffffu, mx1, 2));
        float mn0 = fmaxf(m0, mx0), mn1 = fmaxf(m1, mx1);

        uint32_t pa[4][4];
        float sum0 = 0.f, sum1 = 0.f;
        #pragma unroll
        for (int np = 0; np < 4; np++) {
            float p00 = exp2f(s[2*np][0]   - mn0), p01 = exp2f(s[2*np][1]   - mn0);
            float p02 = exp2f(s[2*np][2]   - mn1), p03 = exp2f(s[2*np][3]   - mn1);
            float p10 = exp2f(s[2*np+1][0] - mn0), p11 = exp2f(s[2*np+1][1] - mn0);
            float p12 = exp2f(s[2*np+1][2] - mn1), p13 = exp2f(s[2*np+1][3] - mn1);
            sum0 += p00 + p01 + p10 + p11;
            sum1 += p02 + p03 + p12 + p13;
            pa[np][0] = h2u(p00, p01);
            pa[np][1] = h2u(p02, p03);
            pa[np][2] = h2u(p10, p11);
            pa[np][3] = h2u(p12, p13);
        }
        sum0 += __shfl_xor_sync(0xffffffffu, sum0, 1);
        sum0 += __shfl_xor_sync(0xffffffffu, sum0, 2);
        sum1 += __shfl_xor_sync(0xffffffffu, sum1, 1);
        sum1 += __shfl_xor_sync(0xffffffffu, sum1, 2);

        float c0 = exp2f(m0 - mn0), c1 = exp2f(m1 - mn1);
        l0 = l0 * c0 + sum0;
        l1 = l1 * c1 + sum1;
        m0 = mn0; m1 = mn1;
        #pragma unroll
        for (int nf = 0; nf < 8; nf++) {
            o[nf][0] *= c0; o[nf][1] *= c0; o[nf][2] *= c1; o[nf][3] *= c1;
        }

        {
            uint32_t va = sb + FW_V + cur * KVS + lmo;
            #pragma unroll
            for (int kf = 0; kf < 4; kf++) {
                #pragma unroll
                for (int np = 0; np < 4; np++) {
                    uint32_t bv[4];
                    ldsm4t(bv, va + (uint32_t)(kf * 16 * 72) * 2 + np * 32);
                    uint32_t b0[2] = { bv[0], bv[1] };
                    uint32_t b1[2] = { bv[2], bv[3] };
                    mma16816(o[2*np],   pa[kf], b0);
                    mma16816(o[2*np+1], pa[kf], b1);
                }
            }
        }

        if (kb + 1 < nkb) CPA_WAIT0();
        __syncthreads();
    }

    {
        float il0 = 1.f / l0, il1 = 1.f / l1;
        __half* Og  = g_Ath + ((size_t)b * S_ + rq0) * D_ + h * DK_ + cc0;
        __half* Og8 = Og + 8 * D_;
        #pragma unroll
        for (int nf = 0; nf < 8; nf++) {
            *(__half2*)(Og  + nf * 8) = __floats2half2_rn(o[nf][0] * il0, o[nf][1] * il0);
            *(__half2*)(Og8 + nf * 8) = __floats2half2_rn(o[nf][2] * il1, o[nf][3] * il1);
        }
    }
}

// ---------------------------------------------------------------------------
// Host launcher
// ---------------------------------------------------------------------------
extern "C" void kernel_launch(void* const* d_in, const int* in_sizes, int n_in,
                              void* d_out, int out_size)
{
    const float* q  = (const float*)d_in[0];
    const float* k  = (const float*)d_in[1];
    const float* v  = (const float*)d_in[2];
    const float* Wq = (const float*)d_in[4];
    const float* bq = (const float*)d_in[5];
    const float* Wk = (const float*)d_in[6];
    const float* bk = (const float*)d_in[7];
    const float* Wv = (const float*)d_in[8];
    const float* bv = (const float*)d_in[9];
    const float* Wo = (const float*)d_in[10];
    const float* bo = (const float*)d_in[11];
    float* out = (float*)d_out;

    table_kernel<<<S_ * 32 / 256, 256>>>();
    tohalf3_kernel<<<MTOT * D_ / 4 / 256, 256>>>(q, k, v);
    transpose_kernel<<<dim3(32, 32, 4), dim3(32, 8)>>>(Wq, Wk, Wv, Wo);

    size_t gsmem = 4 * GBUF * 2;                // 73728 B
    cudaFuncSetAttribute(qkv_kernel,   cudaFuncAttributeMaxDynamicSharedMemorySize, (int)gsmem);
    cudaFuncSetAttribute(oproj_kernel, cudaFuncAttributeMaxDynamicSharedMemorySize, (int)gsmem);
    qkv_kernel<<<dim3(8, 32, 3), 256, gsmem>>>(bq, bk, bv);

    size_t fsmem = FW_TOT;                      // 55296 B
    cudaFuncSetAttribute(flash_kernel, cudaFuncAttributeMaxDynamicSharedMemorySize, (int)fsmem);
    flash_kernel<<<512, 256, fsmem>>>();

    oproj_kernel<<<dim3(8, 32), 256, gsmem>>>(bo, out);
}

// round 10
// speedup vs baseline: 6.9436x; 1.0092x over previous
#include <cuda_runtime.h>
#include <mma.h>
#include <cuda_fp16.h>
#include <math.h>
#include <stdint.h>

using namespace nvcuda;

#define B_   2
#define S_   2048
#define D_   1024
#define H_   16
#define DK_  64
#define MTOT (B_ * S_)   // 4096
#define LOG2E 1.44269504088896340736f

__device__ __half g_qh[MTOT * D_];
__device__ __half g_kh[MTOT * D_];
__device__ __half g_vh[MTOT * D_];
__device__ __half g_Wh[4 * D_ * D_];    // transposed weights [N,K], fp16
__device__ __half g_Qh[MTOT * D_];      // projected Q (rope, x 0.125*log2e)
__device__ __half g_Kh[MTOT * D_];      // projected K (rope)
__device__ __half g_Vh[MTOT * D_];      // projected V
__device__ __half g_Ath[MTOT * D_];     // attention output
__device__ float  g_cos[S_ * 32];
__device__ float  g_sin[S_ * 32];

__device__ __forceinline__ uint32_t smem_u32(const void* p) {
    uint32_t a;
    asm("{ .reg .u64 t; cvta.to.shared.u64 t, %1; cvt.u32.u64 %0, t; }" : "=r"(a) : "l"(p));
    return a;
}
__device__ __forceinline__ void cpa16(uint32_t dst, const void* src) {
    asm volatile("cp.async.cg.shared.global [%0], [%1], 16;" :: "r"(dst), "l"(src) : "memory");
}
#define CPA_COMMIT() asm volatile("cp.async.commit_group;" ::: "memory")
#define CPA_WAIT1()  asm volatile("cp.async.wait_group 1;" ::: "memory")
#define CPA_WAIT0()  asm volatile("cp.async.wait_group 0;" ::: "memory")

__device__ __forceinline__ void mma16816(float* c, const uint32_t* a, const uint32_t* b) {
    asm volatile("mma.sync.aligned.m16n8k16.row.col.f32.f16.f16.f32 "
        "{%0,%1,%2,%3}, {%4,%5,%6,%7}, {%8,%9}, {%0,%1,%2,%3};"
        : "+f"(c[0]), "+f"(c[1]), "+f"(c[2]), "+f"(c[3])
        : "r"(a[0]), "r"(a[1]), "r"(a[2]), "r"(a[3]), "r"(b[0]), "r"(b[1]));
}
__device__ __forceinline__ void ldsm4(uint32_t* r, uint32_t addr) {
    asm volatile("ldmatrix.sync.aligned.m8n8.x4.shared.b16 {%0,%1,%2,%3}, [%4];"
        : "=r"(r[0]), "=r"(r[1]), "=r"(r[2]), "=r"(r[3]) : "r"(addr));
}
__device__ __forceinline__ void ldsm4t(uint32_t* r, uint32_t addr) {
    asm volatile("ldmatrix.sync.aligned.m8n8.x4.trans.shared.b16 {%0,%1,%2,%3}, [%4];"
        : "=r"(r[0]), "=r"(r[1]), "=r"(r[2]), "=r"(r[3]) : "r"(addr));
}
__device__ __forceinline__ uint32_t h2u(float x, float y) {
    __half2 h = __floats2half2_rn(x, y);
    return *(uint32_t*)&h;
}

// ---------------------------------------------------------------------------
// Prep
// ---------------------------------------------------------------------------
__global__ void table_kernel()
{
    int idx = blockIdx.x * blockDim.x + threadIdx.x;   // 65536
    int i = idx & 31;
    int s = idx >> 5;
    double inv = exp(-((double)i / 32.0) * log(10000.0));
    double ang = (double)s * inv;
    g_cos[idx] = (float)cos(ang);
    g_sin[idx] = (float)sin(ang);
}

__global__ void tohalf3_kernel(const float* __restrict__ q, const float* __restrict__ k,
                               const float* __restrict__ v)
{
    int i = blockIdx.x * blockDim.x + threadIdx.x;
    float4 a = ((const float4*)q)[i];
    float4 b = ((const float4*)k)[i];
    float4 c = ((const float4*)v)[i];
    ((__half2*)g_qh)[i*2]   = __floats2half2_rn(a.x, a.y);
    ((__half2*)g_qh)[i*2+1] = __floats2half2_rn(a.z, a.w);
    ((__half2*)g_kh)[i*2]   = __floats2half2_rn(b.x, b.y);
    ((__half2*)g_kh)[i*2+1] = __floats2half2_rn(b.z, b.w);
    ((__half2*)g_vh)[i*2]   = __floats2half2_rn(c.x, c.y);
    ((__half2*)g_vh)[i*2+1] = __floats2half2_rn(c.z, c.w);
}

__global__ void transpose_kernel(const float* __restrict__ W0, const float* __restrict__ W1,
                                 const float* __restrict__ W2, const float* __restrict__ W3)
{
    __shared__ float t[32][33];
    const float* W = (blockIdx.z == 0) ? W0 : (blockIdx.z == 1) ? W1 : (blockIdx.z == 2) ? W2 : W3;
    __half* Wt = g_Wh + (size_t)blockIdx.z * D_ * D_;
    int tx = threadIdx.x, ty = threadIdx.y;
    int x = blockIdx.x * 32 + tx;
    int y = blockIdx.y * 32 + ty;
    #pragma unroll
    for (int j = 0; j < 32; j += 8)
        t[ty + j][tx] = W[(size_t)(y + j) * D_ + x];
    __syncthreads();
    int x2 = blockIdx.y * 32 + tx;
    int y2 = blockIdx.x * 32 + ty;
    #pragma unroll
    for (int j = 0; j < 32; j += 8)
        Wt[(size_t)(y2 + j) * D_ + x2] = __float2half_rn(t[tx][ty + j]);
}

// ---------------------------------------------------------------------------
// fp16 GEMM: 128x128 tile, BK=64, 3-stage cp.async pipeline, ONE sync/stage.
// smem: 3 x (A[128][72] + B[128][72]) = 110592 B; 2 CTA/SM.
// ---------------------------------------------------------------------------
#define GLD 72                   // stage row stride (halves)
#define GBUF 9216                // one matrix buffer (halves)
#define GSTAGE_H 18432           // one stage (A+B) in halves
#define GSTAGE_B 36864           // one stage in bytes

__device__ __forceinline__ void gemm_body(
    const __half* __restrict__ A, const __half* __restrict__ Bt,
    const float* __restrict__ bias, float* __restrict__ Cf, __half* __restrict__ Ch,
    int rope, float oscale)
{
    extern __shared__ __align__(128) char smc[];
    __half* smh = (__half*)smc;
    float (*Cs)[132] = (float(*)[132])smc;

    const int tid = threadIdx.x;
    const int wid = tid >> 5;
    const int wr  = wid >> 2;    // 0..1 -> rows wr*64
    const int wc  = wid & 3;     // 0..3 -> cols wc*32
    const int bm  = blockIdx.y * 128;
    const int bn  = blockIdx.x * 128;

    const uint32_t sb = smem_u32(smc);

    const int r0 = tid >> 3;     // rows r0 + 32j
    const int c8 = tid & 7;
    const __half* Ag = A  + (size_t)(bm + r0) * D_ + c8 * 8;
    const __half* Bg = Bt + (size_t)(bn + r0) * D_ + c8 * 8;
    uint32_t dstA[4], dstB[4];
    #pragma unroll
    for (int j = 0; j < 4; j++) {
        dstA[j] = sb + (uint32_t)((r0 + 32 * j) * GLD + c8 * 8) * 2;
        dstB[j] = dstA[j] + GBUF * 2;
    }

    wmma::fragment<wmma::accumulator, 16, 16, 16, float> acc[4][2];
    #pragma unroll
    for (int s = 0; s < 4; s++)
        #pragma unroll
        for (int f = 0; f < 2; f++) wmma::fill_fragment(acc[s][f], 0.0f);

    // Prologue: stages 0 and 1 as separate groups
    #pragma unroll
    for (int j = 0; j < 4; j++) {
        cpa16(dstA[j], Ag + (size_t)j * 32 * D_);
        cpa16(dstB[j], Bg + (size_t)j * 32 * D_);
    }
    CPA_COMMIT();
    #pragma unroll
    for (int j = 0; j < 4; j++) {
        cpa16(dstA[j] + GSTAGE_B, Ag + (size_t)j * 32 * D_ + 64);
        cpa16(dstB[j] + GSTAGE_B, Bg + (size_t)j * 32 * D_ + 64);
    }
    CPA_COMMIT();

    for (int s = 0; s < 16; s++) {
        if (s < 15) CPA_WAIT1(); else CPA_WAIT0();
        __syncthreads();

        if (s + 2 < 16) {
            const uint32_t off = (uint32_t)((s + 2) % 3) * GSTAGE_B;
            #pragma unroll
            for (int j = 0; j < 4; j++) {
                cpa16(dstA[j] + off, Ag + (size_t)j * 32 * D_ + (s + 2) * 64);
                cpa16(dstB[j] + off, Bg + (size_t)j * 32 * D_ + (s + 2) * 64);
            }
            CPA_COMMIT();
        }

        const __half* As = smh + (s % 3) * GSTAGE_H;
        const __half* Bs = As + GBUF;
        #pragma unroll
        for (int ks = 0; ks < 4; ks++) {
            wmma::fragment<wmma::matrix_a, 16, 16, 16, __half, wmma::row_major> a[4];
            wmma::fragment<wmma::matrix_b, 16, 16, 16, __half, wmma::col_major> bf[2];
            #pragma unroll
            for (int t = 0; t < 4; t++)
                wmma::load_matrix_sync(a[t], &As[(wr * 64 + t * 16) * GLD + ks * 16], GLD);
            #pragma unroll
            for (int f = 0; f < 2; f++)
                wmma::load_matrix_sync(bf[f], &Bs[(wc * 32 + f * 16) * GLD + ks * 16], GLD);
            #pragma unroll
            for (int t = 0; t < 4; t++)
                #pragma unroll
                for (int f = 0; f < 2; f++)
                    wmma::mma_sync(acc[t][f], a[t], bf[f], acc[t][f]);
        }
    }
    __syncthreads();   // protect smem (epilogue alias) from in-flight readers

    // Epilogue
    #pragma unroll
    for (int t = 0; t < 4; t++)
        #pragma unroll
        for (int f = 0; f < 2; f++)
            wmma::store_matrix_sync(&Cs[wr * 64 + t * 16][wc * 32 + f * 16], acc[t][f], 132,
                                    wmma::mem_row_major);
    __syncthreads();

    if (rope) {
        for (int i = tid; i < 128 * 16; i += 256) {
            int r  = i >> 4;
            int rest = i & 15;
            int hp = rest >> 3;
            int c  = hp * 64 + (rest & 7) * 4;
            int wcn = (rest & 7) * 4;
            int sg = (bm + r) & (S_ - 1);
            float4 v1 = *(float4*)&Cs[r][c];
            float4 v2 = *(float4*)&Cs[r][c + 32];
            float4 cw = *(const float4*)(g_cos + sg * 32 + wcn);
            float4 sw = *(const float4*)(g_sin + sg * 32 + wcn);
            float4 b1 = *(const float4*)(bias + bn + c);
            float4 b2 = *(const float4*)(bias + bn + c + 32);
            float4 o1, o2;
            o1.x = (v1.x * cw.x - v2.x * sw.x + b1.x) * oscale;
            o2.x = (v2.x * cw.x + v1.x * sw.x + b2.x) * oscale;
            o1.y = (v1.y * cw.y - v2.y * sw.y + b1.y) * oscale;
            o2.y = (v2.y * cw.y + v1.y * sw.y + b2.y) * oscale;
            o1.z = (v1.z * cw.z - v2.z * sw.z + b1.z) * oscale;
            o2.z = (v2.z * cw.z + v1.z * sw.z + b2.z) * oscale;
            o1.w = (v1.w * cw.w - v2.w * sw.w + b1.w) * oscale;
            o2.w = (v2.w * cw.w + v1.w * sw.w + b2.w) * oscale;
            __half* p1 = Ch + (size_t)(bm + r) * D_ + bn + c;
            __half* p2 = p1 + 32;
            *(__half2*)(p1)     = __floats2half2_rn(o1.x, o1.y);
            *(__half2*)(p1 + 2) = __floats2half2_rn(o1.z, o1.w);
            *(__half2*)(p2)     = __floats2half2_rn(o2.x, o2.y);
            *(__half2*)(p2 + 2) = __floats2half2_rn(o2.z, o2.w);
        }
    } else if (Ch) {
        for (int i = tid; i < 128 * 32; i += 256) {
            int r = i >> 5;
            int c = (i & 31) * 4;
            float4 v  = *(float4*)&Cs[r][c];
            float4 bb = *(const float4*)(bias + bn + c);
            v.x += bb.x; v.y += bb.y; v.z += bb.z; v.w += bb.w;
            __half* p = Ch + (size_t)(bm + r) * D_ + bn + c;
            *(__half2*)(p)     = __floats2half2_rn(v.x, v.y);
            *(__half2*)(p + 2) = __floats2half2_rn(v.z, v.w);
        }
    } else {
        for (int i = tid; i < 128 * 32; i += 256) {
            int r = i >> 5;
            int c = (i & 31) * 4;
            float4 v  = *(float4*)&Cs[r][c];
            float4 bb = *(const float4*)(bias + bn + c);
            v.x += bb.x; v.y += bb.y; v.z += bb.z; v.w += bb.w;
            *(float4*)(Cf + (size_t)(bm + r) * D_ + bn + c) = v;
        }
    }
}

__global__ __launch_bounds__(256, 2) void qkv_kernel(
    const float* __restrict__ bq, const float* __restrict__ bk, const float* __restrict__ bv)
{
    if (blockIdx.z == 0)      gemm_body(g_qh, g_Wh,               bq, nullptr, g_Qh, 1, 0.125f * LOG2E);
    else if (blockIdx.z == 1) gemm_body(g_kh, g_Wh + 1 * D_ * D_, bk, nullptr, g_Kh, 1, 1.0f);
    else                      gemm_body(g_vh, g_Wh + 2 * D_ * D_, bv, nullptr, g_Vh, 0, 1.0f);
}

__global__ __launch_bounds__(256, 2) void oproj_kernel(
    const float* __restrict__ bo, float* __restrict__ out)
{
    gemm_body(g_Ath, g_Wh + 3 * D_ * D_, bo, out, nullptr, 0, 1.0f);
}

// ---------------------------------------------------------------------------
// Flash attention FA2 (registers), base-2 softmax, LPT grid, warp block-skip.
// ---------------------------------------------------------------------------
#define FW_Q 0               // 128 x 72 halves = 18432 B
#define FW_K 18432           // 2 x (64 x 72) halves
#define FW_V 36864
#define FW_TOT 55296
#define KVS 9216             // one K/V buffer bytes

__global__ __launch_bounds__(256, 2) void flash_kernel()
{
    extern __shared__ __align__(128) char smc[];
    const int idx = blockIdx.x;
    const int qb = 15 - (idx >> 5);
    const int h  = idx & 15;
    const int b  = (idx >> 4) & 1;

    const int tid  = threadIdx.x;
    const int w    = tid >> 5;
    const int lane = tid & 31;
    const int q0   = qb * 128;
    const int w16  = w * 16;

    const uint32_t sb = smem_u32(smc);
    const __half* Qg = g_Qh + ((size_t)b * S_ + q0) * D_ + h * DK_;
    const __half* Kb = g_Kh + ((size_t)b * S_) * D_ + h * DK_;
    const __half* Vb = g_Vh + ((size_t)b * S_) * D_ + h * DK_;

    #pragma unroll
    for (int j = 0; j < 4; j++) {
        int i = tid + j * 256;
        int r = i >> 3, c8 = i & 7;
        cpa16(sb + FW_Q + (uint32_t)(r * 72 + c8 * 8) * 2, Qg + (size_t)r * D_ + c8 * 8);
    }
    #pragma unroll
    for (int j = 0; j < 2; j++) {
        int i = tid + j * 256;
        int r = i >> 3, c8 = i & 7;
        cpa16(sb + FW_K + (uint32_t)(r * 72 + c8 * 8) * 2, Kb + (size_t)r * D_ + c8 * 8);
        cpa16(sb + FW_V + (uint32_t)(r * 72 + c8 * 8) * 2, Vb + (size_t)r * D_ + c8 * 8);
    }
    CPA_COMMIT();
    CPA_WAIT0();
    __syncthreads();

    uint32_t aq[4][4];
    {
        uint32_t qa = sb + FW_Q +
            (uint32_t)((w16 + (lane & 15)) * 72 + ((lane & 16) ? 8 : 0)) * 2;
        #pragma unroll
        for (int kf = 0; kf < 4; kf++) ldsm4(aq[kf], qa + kf * 32);
    }

    float o[8][4];
    #pragma unroll
    for (int nf = 0; nf < 8; nf++) { o[nf][0]=0.f; o[nf][1]=0.f; o[nf][2]=0.f; o[nf][3]=0.f; }
    float m0 = -1e30f, m1 = -1e30f, l0 = 0.f, l1 = 0.f;

    const int nkb = 2 * qb + 2;
    const int rq0 = q0 + w16 + (lane >> 2);
    const int cc0 = (lane & 3) * 2;
    const uint32_t lmo = (uint32_t)((lane & 15) * 72 + ((lane & 16) ? 8 : 0)) * 2;

    for (int kb = 0; kb < nkb; kb++) {
        const int cur = kb & 1, nxt = cur ^ 1;

        if (kb + 1 < nkb) {
            const __half* Kg = Kb + (size_t)(kb + 1) * 64 * D_;
            const __half* Vg = Vb + (size_t)(kb + 1) * 64 * D_;
            #pragma unroll
            for (int j = 0; j < 2; j++) {
                int i = tid + j * 256;
                int r = i >> 3, c8 = i & 7;
                uint32_t off = (uint32_t)(nxt * KVS + (r * 72 + c8 * 8) * 2);
                cpa16(sb + FW_K + off, Kg + (size_t)r * D_ + c8 * 8);
                cpa16(sb + FW_V + off, Vg + (size_t)r * D_ + c8 * 8);
            }
            CPA_COMMIT();
        }

        // Warp-level skip: entire 16-row strip above the diagonal for this block
        const bool active = (kb * 64 <= q0 + w16 + 15);
        if (active) {
            float s[8][4];
            #pragma unroll
            for (int nf = 0; nf < 8; nf++) { s[nf][0]=0.f; s[nf][1]=0.f; s[nf][2]=0.f; s[nf][3]=0.f; }
            {
                uint32_t ka = sb + FW_K + cur * KVS + lmo;
                #pragma unroll
                for (int kf = 0; kf < 4; kf++) {
                    #pragma unroll
                    for (int np = 0; np < 4; np++) {
                        uint32_t bk[4];
                        ldsm4(bk, ka + (uint32_t)(np * 16 * 72) * 2 + kf * 32);
                        uint32_t b0[2] = { bk[0], bk[2] };
                        uint32_t b1[2] = { bk[1], bk[3] };
                        mma16816(s[2*np],   aq[kf], b0);
                        mma16816(s[2*np+1], aq[kf], b1);
                    }
                }
            }

            if (kb >= 2 * qb) {
                #pragma unroll
                for (int nf = 0; nf < 8; nf++) {
                    int c = kb * 64 + nf * 8 + cc0;
                    if (c     > rq0)     s[nf][0] = -1e30f;
                    if (c + 1 > rq0)     s[nf][1] = -1e30f;
                    if (c     > rq0 + 8) s[nf][2] = -1e30f;
                    if (c + 1 > rq0 + 8) s[nf][3] = -1e30f;
                }
            }

            float mx0 = -1e30f, mx1 = -1e30f;
            #pragma unroll
            for (int nf = 0; nf < 8; nf++) {
                mx0 = fmaxf(mx0, fmaxf(s[nf][0], s[nf][1]));
                mx1 = fmaxf(mx1, fmaxf(s[nf][2], s[nf][3]));
            }
            mx0 = fmaxf(mx0, __shfl_xor_sync(0xffffffffu, mx0, 1));
            mx0 = fmaxf(mx0, __shfl_xor_sync(0xffffffffu, mx0, 2));
            mx1 = fmaxf(mx1, __shfl_xor_sync(0xffffffffu, mx1, 1));
            mx1 = fmaxf(mx1, __shfl_xor_sync(0xffffffffu, mx1, 2));
            float mn0 = fmaxf(m0, mx0), mn1 = fmaxf(m1, mx1);

            uint32_t pa[4][4];
            float sum0 = 0.f, sum1 = 0.f;
            #pragma unroll
            for (int np = 0; np < 4; np++) {
                float p00 = exp2f(s[2*np][0]   - mn0), p01 = exp2f(s[2*np][1]   - mn0);
                float p02 = exp2f(s[2*np][2]   - mn1), p03 = exp2f(s[2*np][3]   - mn1);
                float p10 = exp2f(s[2*np+1][0] - mn0), p11 = exp2f(s[2*np+1][1] - mn0);
                float p12 = exp2f(s[2*np+1][2] - mn1), p13 = exp2f(s[2*np+1][3] - mn1);
                sum0 += p00 + p01 + p10 + p11;
                sum1 += p02 + p03 + p12 + p13;
                pa[np][0] = h2u(p00, p01);
                pa[np][1] = h2u(p02, p03);
                pa[np][2] = h2u(p10, p11);
                pa[np][3] = h2u(p12, p13);
            }
            sum0 += __shfl_xor_sync(0xffffffffu, sum0, 1);
            sum0 += __shfl_xor_sync(0xffffffffu, sum0, 2);
            sum1 += __shfl_xor_sync(0xffffffffu, sum1, 1);
            sum1 += __shfl_xor_sync(0xffffffffu, sum1, 2);

            float c0 = exp2f(m0 - mn0), c1 = exp2f(m1 - mn1);
            l0 = l0 * c0 + sum0;
            l1 = l1 * c1 + sum1;
            m0 = mn0; m1 = mn1;
            #pragma unroll
            for (int nf = 0; nf < 8; nf++) {
                o[nf][0] *= c0; o[nf][1] *= c0; o[nf][2] *= c1; o[nf][3] *= c1;
            }

            {
                uint32_t va = sb + FW_V + cur * KVS + lmo;
                #pragma unroll
                for (int kf = 0; kf < 4; kf++) {
                    #pragma unroll
                    for (int np = 0; np < 4; np++) {
                        uint32_t bv[4];
                        ldsm4t(bv, va + (uint32_t)(kf * 16 * 72) * 2 + np * 32);
                        uint32_t b0[2] = { bv[0], bv[1] };
                        uint32_t b1[2] = { bv[2], bv[3] };
                        mma16816(o[2*np],   pa[kf], b0);
                        mma16816(o[2*np+1], pa[kf], b1);
                    }
                }
            }
        }

        if (kb + 1 < nkb) CPA_WAIT0();
        __syncthreads();
    }

    {
        float il0 = 1.f / l0, il1 = 1.f / l1;
        __half* Og  = g_Ath + ((size_t)b * S_ + rq0) * D_ + h * DK_ + cc0;
        __half* Og8 = Og + 8 * D_;
        #pragma unroll
        for (int nf = 0; nf < 8; nf++) {
            *(__half2*)(Og  + nf * 8) = __floats2half2_rn(o[nf][0] * il0, o[nf][1] * il0);
            *(__half2*)(Og8 + nf * 8) = __floats2half2_rn(o[nf][2] * il1, o[nf][3] * il1);
        }
    }
}

// ---------------------------------------------------------------------------
// Host launcher
// ---------------------------------------------------------------------------
extern "C" void kernel_launch(void* const* d_in, const int* in_sizes, int n_in,
                              void* d_out, int out_size)
{
    const float* q  = (const float*)d_in[0];
    const float* k  = (const float*)d_in[1];
    const float* v  = (const float*)d_in[2];
    const float* Wq = (const float*)d_in[4];
    const float* bq = (const float*)d_in[5];
    const float* Wk = (const float*)d_in[6];
    const float* bk = (const float*)d_in[7];
    const float* Wv = (const float*)d_in[8];
    const float* bv = (const float*)d_in[9];
    const float* Wo = (const float*)d_in[10];
    const float* bo = (const float*)d_in[11];
    float* out = (float*)d_out;

    table_kernel<<<S_ * 32 / 256, 256>>>();
    tohalf3_kernel<<<MTOT * D_ / 4 / 256, 256>>>(q, k, v);
    transpose_kernel<<<dim3(32, 32, 4), dim3(32, 8)>>>(Wq, Wk, Wv, Wo);

    size_t gsmem = 3 * GSTAGE_B;                // 110592 B
    cudaFuncSetAttribute(qkv_kernel,   cudaFuncAttributeMaxDynamicSharedMemorySize, (int)gsmem);
    cudaFuncSetAttribute(oproj_kernel, cudaFuncAttributeMaxDynamicSharedMemorySize, (int)gsmem);
    qkv_kernel<<<dim3(8, 32, 3), 256, gsmem>>>(bq, bk, bv);

    size_t fsmem = FW_TOT;                      // 55296 B
    cudaFuncSetAttribute(flash_kernel, cudaFuncAttributeMaxDynamicSharedMemorySize, (int)fsmem);
    flash_kernel<<<512, 256, fsmem>>>();

    oproj_kernel<<<dim3(8, 32), 256, gsmem>>>(bo, out);
}